// round 12
// baseline (speedup 1.0000x reference)
#include <cuda_runtime.h>
#include <cuda_fp16.h>
#include <math.h>
#include <stdint.h>

#define NN   4096
#define KF   512     // IN_F
#define CF   512     // OUT_F * N_HEADS
#define NH   8
#define OF   64

// ---- scratch (device globals; no allocation allowed) ----
__device__ __half   g_W16T[CF * KF];          // 512 KB  W fp16 transposed [c][k]
__device__ float    g_wst[16 * KF];           // 32 KB   ws_t[h*2+d][k]
__device__ __half   g_Whf16[(size_t)NN * CF]; // 4 MB    Wh fp16 [n][c]
__device__ __half   g_WhT[NH * OF * NN];      // 4 MB    values transposed [h][f][n]
__device__ unsigned g_bits[NN * 128];         // 2 MB    packed adj
__device__ float4   g_attrS[NH * NN];         // (src, Es/16, Es2/16, 0)
__device__ uint4    g_attrP[NH * (NN / 2)];   // per j-pair: (dst2, Ed2, Ed22, pad)

__device__ __forceinline__ uint32_t smem_u32(const void* p) {
    uint32_t a;
    asm("{ .reg .u64 t; cvta.to.shared.u64 t, %1; cvt.u32.u64 %0, t; }" : "=r"(a) : "l"(p));
    return a;
}
__device__ __forceinline__ unsigned h2u(__half2 v) {
    return *reinterpret_cast<unsigned*>(&v);
}
__device__ __forceinline__ void ldsm4(uint32_t& r0, uint32_t& r1, uint32_t& r2, uint32_t& r3,
                                      uint32_t addr) {
    asm volatile("ldmatrix.sync.aligned.m8n8.x4.shared.b16 {%0,%1,%2,%3}, [%4];"
                 : "=r"(r0), "=r"(r1), "=r"(r2), "=r"(r3) : "r"(addr));
}
__device__ __forceinline__ void mma16816(float* d, const uint32_t* a, const uint32_t* b) {
    asm volatile(
        "mma.sync.aligned.m16n8k16.row.col.f32.f16.f16.f32 "
        "{%0,%1,%2,%3}, {%4,%5,%6,%7}, {%8,%9}, {%0,%1,%2,%3};"
        : "+f"(d[0]), "+f"(d[1]), "+f"(d[2]), "+f"(d[3])
        : "r"(a[0]), "r"(a[1]), "r"(a[2]), "r"(a[3]), "r"(b[0]), "r"(b[1]));
}

// ============================================================
__global__ void k_nop() {}   // ncu launch-index shim

// ============================================================
// W -> W16T (fp16, transposed [c][k])
// ============================================================
__global__ __launch_bounds__(256) void k_cvtW(const float* __restrict__ W) {
    __shared__ float Ts[32][33];
    int k0 = blockIdx.y * 32, c0 = blockIdx.x * 32;
    int tx = threadIdx.x & 31, ty = threadIdx.x >> 5;
#pragma unroll
    for (int q = 0; q < 4; q++) {
        int r = ty + q * 8;
        Ts[r][tx] = W[(k0 + r) * CF + c0 + tx];
    }
    __syncthreads();
#pragma unroll
    for (int q = 0; q < 4; q++) {
        int cy = ty + q * 8;
        g_W16T[(c0 + cy) * KF + k0 + tx] = __float2half(Ts[tx][cy]);
    }
}

// ============================================================
// ws_t[hd][k] = sum_f W[k][h*64+f] * a[d*64+f]  (exact fp32)
// ============================================================
__global__ __launch_bounds__(256) void k_ws(const float* __restrict__ W,
                                            const float* __restrict__ a) {
    __shared__ float as[128];
    if (threadIdx.x < 128) as[threadIdx.x] = a[threadIdx.x];
    __syncthreads();
    int idx = blockIdx.x * 256 + threadIdx.x;
    int hd = idx & 15, k = idx >> 4;
    int h = hd >> 1, d = hd & 1;
    const float* wr = W + k * CF + h * OF;
    const float* av = as + d * OF;
    float s = 0.f;
#pragma unroll 16
    for (int f = 0; f < OF; f++) s += wr[f] * av[f];
    g_wst[hd * KF + k] = s;
}

// ============================================================
// Whf16 = h @ W via HMMA
// ============================================================
#define GASTR 72
#define GBSTR 72
__global__ __launch_bounds__(256) void k_gemm16(const float* __restrict__ h) {
    __shared__ __half As[128 * GASTR];
    __shared__ __half Bs[64 * GBSTR];
    int tid = threadIdx.x, wid = tid >> 5, lane = tid & 31;
    int n0 = blockIdx.y * 128, c0 = blockIdx.x * 64;
    float acc[8][4];
#pragma unroll
    for (int nt = 0; nt < 8; nt++)
#pragma unroll
        for (int q = 0; q < 4; q++) acc[nt][q] = 0.f;
    uint32_t aAddr = smem_u32(As) + (wid * 16 + (lane & 15)) * (GASTR * 2) + (lane >> 4) * 16;
    uint32_t bAddr = smem_u32(Bs) + (((lane & 7) + ((lane >> 4) & 1) * 8)) * (GBSTR * 2)
                   + ((lane >> 3) & 1) * 16;

    for (int k0 = 0; k0 < KF; k0 += 64) {
        __syncthreads();
#pragma unroll
        for (int q = 0; q < 8; q++) {
            int lin = tid + q * 256;
            int rr = lin >> 4, kq = (lin & 15) * 4;
            float4 v = *(const float4*)(h + (size_t)(n0 + rr) * KF + k0 + kq);
            *(__half2*)&As[rr * GASTR + kq]     = __floats2half2_rn(v.x, v.y);
            *(__half2*)&As[rr * GASTR + kq + 2] = __floats2half2_rn(v.z, v.w);
        }
#pragma unroll
        for (int q = 0; q < 2; q++) {
            int lin = tid + q * 256;
            int cc = lin >> 3, kq = (lin & 7) * 8;
            uint4 v = *(const uint4*)&g_W16T[(c0 + cc) * KF + k0 + kq];
            *(uint4*)&Bs[cc * GBSTR + kq] = v;
        }
        __syncthreads();
#pragma unroll
        for (int kc = 0; kc < 4; kc++) {
            uint32_t aa[4];
            ldsm4(aa[0], aa[1], aa[2], aa[3], aAddr + kc * 32);
            uint32_t b[16];
#pragma unroll
            for (int nq = 0; nq < 4; nq++)
                ldsm4(b[nq * 4], b[nq * 4 + 1], b[nq * 4 + 2], b[nq * 4 + 3],
                      bAddr + nq * 16 * (GBSTR * 2) + kc * 32);
#pragma unroll
            for (int nt = 0; nt < 8; nt++) mma16816(acc[nt], aa, &b[nt * 2]);
        }
    }
    int r0 = n0 + wid * 16 + (lane >> 2);
    int cb = c0 + (lane & 3) * 2;
#pragma unroll
    for (int nt = 0; nt < 8; nt++) {
        *(__half2*)&g_Whf16[(size_t)r0 * CF + cb + nt * 8] =
            __floats2half2_rn(acc[nt][0], acc[nt][1]);
        *(__half2*)&g_Whf16[(size_t)(r0 + 8) * CF + cb + nt * 8] =
            __floats2half2_rn(acc[nt][2], acc[nt][3]);
    }
}

// ============================================================
// PREP: pack adj bits; attrs via h @ ws_t (exact);
// transpose Whf16 -> WhT (blocks 0..255)
// ============================================================
__global__ __launch_bounds__(256) void k_prep(const int* __restrict__ adj,
                                              const float* __restrict__ hsrc) {
    __shared__ __half Ts[64 * 130];
    int b = blockIdx.x, tid = threadIdx.x;
    int w = tid >> 5, lane = tid & 31;

    // pack adj row b
#pragma unroll
    for (int q = 0; q < 16; q++) {
        int wd = w * 16 + q;
        int j = wd * 32 + lane;
        unsigned bt = __ballot_sync(0xFFFFFFFFu, adj[(size_t)b * NN + j] > 0);
        if (lane == 0) g_bits[b * 128 + wd] = bt;
    }

    // attrs: (node b, head w), exact fp32 via ws_t
    {
        const float* hr  = hsrc + (size_t)b * KF;
        const float* wsS = g_wst + (2 * w) * KF;
        const float* wsD = g_wst + (2 * w + 1) * KF;
        float s = 0.f, d = 0.f;
#pragma unroll
        for (int t = 0; t < 16; t++) {
            float hv = hr[lane + 32 * t];
            s += hv * wsS[lane + 32 * t];
            d += hv * wsD[lane + 32 * t];
        }
#pragma unroll
        for (int o = 16; o; o >>= 1) {
            s += __shfl_xor_sync(0xFFFFFFFFu, s, o);
            d += __shfl_xor_sync(0xFFFFFFFFu, d, o);
        }
        if (lane == 0) {
            g_attrS[w * NN + b] = make_float4(s, expf(s) * 0.0625f, expf(0.2f * s) * 0.0625f, 0.f);
            __half* ap = (__half*)(g_attrP + w * (NN / 2) + (b >> 1)) + (b & 1);
            ap[0] = __float2half(d);
            ap[2] = __float2half(expf(d));
            ap[4] = __float2half(expf(0.2f * d));
        }
    }

    // transpose (blocks 0..255)
    if (b < 256) {
        int hh = b & 7, n0 = (b >> 3) * 128;
        __syncthreads();
#pragma unroll
        for (int q = 0; q < 32; q++) {
            int lin = tid + q * 256;
            int r = lin >> 6, c = lin & 63;
            Ts[c * 130 + r] = g_Whf16[(size_t)(n0 + r) * CF + hh * OF + c];
        }
        __syncthreads();
#pragma unroll
        for (int q = 0; q < 16; q++) {
            int lin = tid + q * 256;
            int f = lin >> 6, n2 = lin & 63;
            __half2 hv = __halves2half2(Ts[f * 130 + n2 * 2], Ts[f * 130 + n2 * 2 + 1]);
            *(__half2*)&g_WhT[(hh * OF + f) * NN + n0 + n2 * 2] = hv;
        }
    }
}

// ============================================================
// GAT: register A-fragments (single buffer, WAR-safe overlap),
// B-only smem double-buffered, occupancy 3 CTAs/SM
// ============================================================
#define BSTR 72
#define BBUF 9216                       // 64*72*2
#define SM_TOT (2 * BBUF + 128)

__global__ __launch_bounds__(256, 3) void k_gat_mma(float* __restrict__ out) {
    extern __shared__ char sm[];
    uint32_t sb = smem_u32(sm);

    int tid = threadIdx.x, wid = tid >> 5, lane = tid & 31;
    int head = blockIdx.x, i0 = blockIdx.y << 7;
    int r = lane >> 2, t = lane & 3;
    int t2 = t << 1;

    int row0 = i0 + wid * 16 + r;
    __half2 isrc[2], ies[2], ies2[2];
    {
        float4 v0 = g_attrS[head * NN + row0];
        float4 v1 = g_attrS[head * NN + row0 + 8];
        isrc[0] = __float2half2_rn(v0.x); ies[0] = __float2half2_rn(v0.y);
        ies2[0] = __float2half2_rn(v0.z);
        isrc[1] = __float2half2_rn(v1.x); ies[1] = __float2half2_rn(v1.y);
        ies2[1] = __float2half2_rn(v1.z);
    }
    const unsigned* bitR0 = g_bits + (size_t)row0 * 128;
    const unsigned* bitR1 = bitR0 + 8 * 128;
    const uint4* attrP = g_attrP + head * (NN / 2);

    float acc[8][4], accz[4];
#pragma unroll
    for (int nt = 0; nt < 8; nt++)
#pragma unroll
        for (int q = 0; q < 4; q++) acc[nt][q] = 0.f;
#pragma unroll
    for (int q = 0; q < 4; q++) accz[q] = 0.f;

    uint32_t bz[2];
    bz[0] = bz[1] = (lane < 4) ? 0x3C003C00u : 0u;

    uint32_t bAddr = sb + (((lane & 7) + ((lane >> 4) & 1) * 8)) * (BSTR * 2)
                   + ((lane >> 3) & 1) * 16;

    auto stageB = [&](int j0, int bufn) {
        __half* Bd = (__half*)(sm + bufn * BBUF);
#pragma unroll
        for (int q = 0; q < 2; q++) {
            int lin = tid + q * 256;
            int f = lin >> 3, c = lin & 7;
            uint4 v = *(const uint4*)&g_WhT[(head * OF + f) * NN + j0 + c * 8];
            *(uint4*)&Bd[f * BSTR + c * 8] = v;
        }
    };

    const __half2 zero2 = __float2half2_rn(0.f);
    auto val = [&](int rowIdx, uint4 J, unsigned sel) -> uint32_t {
        __half2 dst2 = *(__half2*)&J.x;
        __half2 ed   = *(__half2*)&J.y;
        __half2 ed2  = *(__half2*)&J.z;
        unsigned g = __hgt2_mask(__hadd2(isrc[rowIdx], dst2), zero2);
        unsigned v = (h2u(__hmul2(ies[rowIdx], ed)) & g)
                   | (h2u(__hmul2(ies2[rowIdx], ed2)) & ~g);
        unsigned mask = (sel & 1u) * 0x0000FFFFu + (sel & 2u) * 0x7FFF8000u;
        return v & mask;
    };

    auto genFrag = [&](int s1, uint32_t fr[4][4]) {
        uint2 bw0 = *(const uint2*)(bitR0 + s1 * 2);
        uint2 bw1 = *(const uint2*)(bitR1 + s1 * 2);
        const uint4* jp = attrP + (s1 << 5);
#pragma unroll
        for (int kc = 0; kc < 4; kc++) {
            uint4 JA = jp[kc * 8 + t];
            uint4 JB = jp[kc * 8 + 4 + t];
            unsigned w0 = (kc < 2) ? bw0.x : bw0.y;
            unsigned w1 = (kc < 2) ? bw1.x : bw1.y;
            int shA = ((kc & 1) << 4) + t2;
            fr[kc][0] = val(0, JA, (w0 >> shA) & 3u);
            fr[kc][1] = val(1, JA, (w1 >> shA) & 3u);
            fr[kc][2] = val(0, JB, (w0 >> (shA + 8)) & 3u);
            fr[kc][3] = val(1, JB, (w1 >> (shA + 8)) & 3u);
        }
    };

    uint32_t frag[4][4];
    stageB(0, 0);
    genFrag(0, frag);

    for (int s = 0; s < 64; s++) {
        int buf = s & 1;
        __syncthreads();                 // B buf ready; buf^1 free for writes
        if (s < 63) stageB((s + 1) << 6, buf ^ 1);

        // mma on current frag + B buffer, 4 B-regs live at a time
#pragma unroll
        for (int kc = 0; kc < 4; kc++) {
#pragma unroll
            for (int nq = 0; nq < 4; nq++) {
                uint32_t b0, b1, b2, b3;
                ldsm4(b0, b1, b2, b3,
                      bAddr + buf * BBUF + nq * 16 * (BSTR * 2) + kc * 32);
                uint32_t blo[2] = {b0, b1}, bhi[2] = {b2, b3};
                mma16816(acc[nq * 2],     frag[kc], blo);
                mma16816(acc[nq * 2 + 1], frag[kc], bhi);
            }
            mma16816(accz, frag[kc], bz);
        }

        if (s < 63) genFrag(s + 1, frag);  // WAR-safe: mma above already consumed frag
    }

    float z0 = __shfl_sync(0xFFFFFFFFu, accz[0], lane & 28);
    float z1 = __shfl_sync(0xFFFFFFFFu, accz[2], lane & 28);
    float inv0 = 1.0f / z0;
    float inv1 = 1.0f / z1;

    {
        float* o0 = out + (size_t)row0 * CF + head * OF + t2;
        float* o1 = o0 + 8 * CF;
#pragma unroll
        for (int nt = 0; nt < 8; nt++) {
            float v0 = acc[nt][0] * inv0, v1 = acc[nt][1] * inv0;
            float v2 = acc[nt][2] * inv1, v3 = acc[nt][3] * inv1;
            v0 = v0 > 0.f ? v0 : (expf(v0) - 1.0f);
            v1 = v1 > 0.f ? v1 : (expf(v1) - 1.0f);
            v2 = v2 > 0.f ? v2 : (expf(v2) - 1.0f);
            v3 = v3 > 0.f ? v3 : (expf(v3) - 1.0f);
            *(float2*)(o0 + nt * 8) = make_float2(v0, v1);
            *(float2*)(o1 + nt * 8) = make_float2(v2, v3);
        }
    }
}

// ============================================================
extern "C" void kernel_launch(void* const* d_in, const int* in_sizes, int n_in,
                              void* d_out, int out_size) {
    const float* h   = (const float*)d_in[0];
    const int*   adj = (const int*)d_in[1];
    const float* W   = (const float*)d_in[2];
    const float* a   = (const float*)d_in[3];
    float* out = (float*)d_out;

    k_nop<<<1, 32>>>();
    k_cvtW<<<dim3(16, 16), 256>>>(W);
    k_ws<<<32, 256>>>(W, a);
    k_gemm16<<<dim3(8, 32), 256>>>(h);
    k_prep<<<NN, 256>>>(adj, h);

    cudaFuncSetAttribute(k_gat_mma, cudaFuncAttributeMaxDynamicSharedMemorySize, SM_TOT);
    k_gat_mma<<<dim3(NH, NN / 128), 256, SM_TOT>>>(out);
}

// round 13
// speedup vs baseline: 1.3533x; 1.3533x over previous
#include <cuda_runtime.h>
#include <cuda_fp16.h>
#include <math.h>
#include <stdint.h>

#define NN   4096
#define KF   512     // IN_F
#define CF   512     // OUT_F * N_HEADS
#define NH   8
#define OF   64

// ---- scratch (device globals; no allocation allowed) ----
__device__ __half   g_W16T[CF * KF];          // 512 KB  W fp16 transposed [c][k]
__device__ float    g_wst[16 * KF];           // 32 KB   ws_t[h*2+d][k]
__device__ __half   g_Whf16[(size_t)NN * CF]; // 4 MB    Wh fp16 [n][c]
__device__ __half   g_WhT[NH * OF * NN];      // 4 MB    values transposed [h][f][n]
__device__ unsigned g_bits[NN * 128];         // 2 MB    packed adj
__device__ float4   g_attrS[NH * NN];         // (src, Es/16, Es2/16, 0)
__device__ __half2  g_pd[NH * (NN / 2)];      // per j-pair dst2
__device__ __half2  g_pe[NH * (NN / 2)];      // per j-pair Ed2
__device__ __half2  g_pe2[NH * (NN / 2)];     // per j-pair Ed2^0.2

__device__ __forceinline__ uint32_t smem_u32(const void* p) {
    uint32_t a;
    asm("{ .reg .u64 t; cvta.to.shared.u64 t, %1; cvt.u32.u64 %0, t; }" : "=r"(a) : "l"(p));
    return a;
}
__device__ __forceinline__ unsigned h2u(__half2 v) {
    return *reinterpret_cast<unsigned*>(&v);
}
__device__ __forceinline__ void ldsm4(uint32_t& r0, uint32_t& r1, uint32_t& r2, uint32_t& r3,
                                      uint32_t addr) {
    asm volatile("ldmatrix.sync.aligned.m8n8.x4.shared.b16 {%0,%1,%2,%3}, [%4];"
                 : "=r"(r0), "=r"(r1), "=r"(r2), "=r"(r3) : "r"(addr));
}
__device__ __forceinline__ void mma16816(float* d, const uint32_t* a, const uint32_t* b) {
    asm volatile(
        "mma.sync.aligned.m16n8k16.row.col.f32.f16.f16.f32 "
        "{%0,%1,%2,%3}, {%4,%5,%6,%7}, {%8,%9}, {%0,%1,%2,%3};"
        : "+f"(d[0]), "+f"(d[1]), "+f"(d[2]), "+f"(d[3])
        : "r"(a[0]), "r"(a[1]), "r"(a[2]), "r"(a[3]), "r"(b[0]), "r"(b[1]));
}

// ============================================================
__global__ void k_nop() {}   // ncu launch-index shim

// ============================================================
// W -> W16T (fp16, transposed [c][k])
// ============================================================
__global__ __launch_bounds__(256) void k_cvtW(const float* __restrict__ W) {
    __shared__ float Ts[32][33];
    int k0 = blockIdx.y * 32, c0 = blockIdx.x * 32;
    int tx = threadIdx.x & 31, ty = threadIdx.x >> 5;
#pragma unroll
    for (int q = 0; q < 4; q++) {
        int r = ty + q * 8;
        Ts[r][tx] = W[(k0 + r) * CF + c0 + tx];
    }
    __syncthreads();
#pragma unroll
    for (int q = 0; q < 4; q++) {
        int cy = ty + q * 8;
        g_W16T[(c0 + cy) * KF + k0 + tx] = __float2half(Ts[tx][cy]);
    }
}

// ============================================================
// ws_t[hd][k] = sum_f W[k][h*64+f] * a[d*64+f]  (exact fp32)
// ============================================================
__global__ __launch_bounds__(256) void k_ws(const float* __restrict__ W,
                                            const float* __restrict__ a) {
    __shared__ float as[128];
    if (threadIdx.x < 128) as[threadIdx.x] = a[threadIdx.x];
    __syncthreads();
    int idx = blockIdx.x * 256 + threadIdx.x;
    int hd = idx & 15, k = idx >> 4;
    int h = hd >> 1, d = hd & 1;
    const float* wr = W + k * CF + h * OF;
    const float* av = as + d * OF;
    float s = 0.f;
#pragma unroll 16
    for (int f = 0; f < OF; f++) s += wr[f] * av[f];
    g_wst[hd * KF + k] = s;
}

// ============================================================
// Whf16 = h @ W via HMMA
// ============================================================
#define GASTR 72
#define GBSTR 72
__global__ __launch_bounds__(256) void k_gemm16(const float* __restrict__ h) {
    __shared__ __half As[128 * GASTR];
    __shared__ __half Bs[64 * GBSTR];
    int tid = threadIdx.x, wid = tid >> 5, lane = tid & 31;
    int n0 = blockIdx.y * 128, c0 = blockIdx.x * 64;
    float acc[8][4];
#pragma unroll
    for (int nt = 0; nt < 8; nt++)
#pragma unroll
        for (int q = 0; q < 4; q++) acc[nt][q] = 0.f;
    uint32_t aAddr = smem_u32(As) + (wid * 16 + (lane & 15)) * (GASTR * 2) + (lane >> 4) * 16;
    uint32_t bAddr = smem_u32(Bs) + (((lane & 7) + ((lane >> 4) & 1) * 8)) * (GBSTR * 2)
                   + ((lane >> 3) & 1) * 16;

    for (int k0 = 0; k0 < KF; k0 += 64) {
        __syncthreads();
#pragma unroll
        for (int q = 0; q < 8; q++) {
            int lin = tid + q * 256;
            int rr = lin >> 4, kq = (lin & 15) * 4;
            float4 v = *(const float4*)(h + (size_t)(n0 + rr) * KF + k0 + kq);
            *(__half2*)&As[rr * GASTR + kq]     = __floats2half2_rn(v.x, v.y);
            *(__half2*)&As[rr * GASTR + kq + 2] = __floats2half2_rn(v.z, v.w);
        }
#pragma unroll
        for (int q = 0; q < 2; q++) {
            int lin = tid + q * 256;
            int cc = lin >> 3, kq = (lin & 7) * 8;
            uint4 v = *(const uint4*)&g_W16T[(c0 + cc) * KF + k0 + kq];
            *(uint4*)&Bs[cc * GBSTR + kq] = v;
        }
        __syncthreads();
#pragma unroll
        for (int kc = 0; kc < 4; kc++) {
            uint32_t aa[4];
            ldsm4(aa[0], aa[1], aa[2], aa[3], aAddr + kc * 32);
            uint32_t b[16];
#pragma unroll
            for (int nq = 0; nq < 4; nq++)
                ldsm4(b[nq * 4], b[nq * 4 + 1], b[nq * 4 + 2], b[nq * 4 + 3],
                      bAddr + nq * 16 * (GBSTR * 2) + kc * 32);
#pragma unroll
            for (int nt = 0; nt < 8; nt++) mma16816(acc[nt], aa, &b[nt * 2]);
        }
    }
    int r0 = n0 + wid * 16 + (lane >> 2);
    int cb = c0 + (lane & 3) * 2;
#pragma unroll
    for (int nt = 0; nt < 8; nt++) {
        *(__half2*)&g_Whf16[(size_t)r0 * CF + cb + nt * 8] =
            __floats2half2_rn(acc[nt][0], acc[nt][1]);
        *(__half2*)&g_Whf16[(size_t)(r0 + 8) * CF + cb + nt * 8] =
            __floats2half2_rn(acc[nt][2], acc[nt][3]);
    }
}

// ============================================================
// PREP: pack adj bits; attrs via h @ ws_t (exact);
// transpose Whf16 -> WhT (blocks 0..255)
// ============================================================
__global__ __launch_bounds__(256) void k_prep(const int* __restrict__ adj,
                                              const float* __restrict__ hsrc) {
    __shared__ __half Ts[64 * 130];
    int b = blockIdx.x, tid = threadIdx.x;
    int w = tid >> 5, lane = tid & 31;

    // pack adj row b
#pragma unroll
    for (int q = 0; q < 16; q++) {
        int wd = w * 16 + q;
        int j = wd * 32 + lane;
        unsigned bt = __ballot_sync(0xFFFFFFFFu, adj[(size_t)b * NN + j] > 0);
        if (lane == 0) g_bits[b * 128 + wd] = bt;
    }

    // attrs: (node b, head w), exact fp32 via ws_t
    {
        const float* hr  = hsrc + (size_t)b * KF;
        const float* wsS = g_wst + (2 * w) * KF;
        const float* wsD = g_wst + (2 * w + 1) * KF;
        float s = 0.f, d = 0.f;
#pragma unroll
        for (int t = 0; t < 16; t++) {
            float hv = hr[lane + 32 * t];
            s += hv * wsS[lane + 32 * t];
            d += hv * wsD[lane + 32 * t];
        }
#pragma unroll
        for (int o = 16; o; o >>= 1) {
            s += __shfl_xor_sync(0xFFFFFFFFu, s, o);
            d += __shfl_xor_sync(0xFFFFFFFFu, d, o);
        }
        if (lane == 0) {
            g_attrS[w * NN + b] = make_float4(s, expf(s) * 0.0625f, expf(0.2f * s) * 0.0625f, 0.f);
            int pi = w * (NN / 2) + (b >> 1);
            ((__half*)&g_pd[pi])[b & 1]  = __float2half(d);
            ((__half*)&g_pe[pi])[b & 1]  = __float2half(expf(d));
            ((__half*)&g_pe2[pi])[b & 1] = __float2half(expf(0.2f * d));
        }
    }

    // transpose (blocks 0..255)
    if (b < 256) {
        int hh = b & 7, n0 = (b >> 3) * 128;
        __syncthreads();
#pragma unroll
        for (int q = 0; q < 32; q++) {
            int lin = tid + q * 256;
            int r = lin >> 6, c = lin & 63;
            Ts[c * 130 + r] = g_Whf16[(size_t)(n0 + r) * CF + hh * OF + c];
        }
        __syncthreads();
#pragma unroll
        for (int q = 0; q < 16; q++) {
            int lin = tid + q * 256;
            int f = lin >> 6, n2 = lin & 63;
            __half2 hv = __halves2half2(Ts[f * 130 + n2 * 2], Ts[f * 130 + n2 * 2 + 1]);
            *(__half2*)&g_WhT[(hh * OF + f) * NN + n0 + n2 * 2] = hv;
        }
    }
}

// ============================================================
// GAT: register A-fragments with split load/compute prefetch,
// B-only smem double-buffered, 2 CTAs/SM
// ============================================================
#define BSTR 72
#define BBUF 9216                       // 64*72*2
#define SM_TOT (2 * BBUF + 128)

__global__ __launch_bounds__(256, 2) void k_gat_mma(float* __restrict__ out) {
    extern __shared__ char sm[];
    uint32_t sb = smem_u32(sm);

    int tid = threadIdx.x, wid = tid >> 5, lane = tid & 31;
    int head = blockIdx.x, i0 = blockIdx.y << 7;
    int r = lane >> 2, t = lane & 3;
    int t2 = t << 1;

    int row0 = i0 + wid * 16 + r;
    __half2 isrc[2], ies[2], ies2[2];
    {
        float4 v0 = g_attrS[head * NN + row0];
        float4 v1 = g_attrS[head * NN + row0 + 8];
        isrc[0] = __float2half2_rn(v0.x); ies[0] = __float2half2_rn(v0.y);
        ies2[0] = __float2half2_rn(v0.z);
        isrc[1] = __float2half2_rn(v1.x); ies[1] = __float2half2_rn(v1.y);
        ies2[1] = __float2half2_rn(v1.z);
    }
    const unsigned* bitR0 = g_bits + (size_t)row0 * 128;
    const unsigned* bitR1 = bitR0 + 8 * 128;
    const int hpo = head * (NN / 2);

    float acc[8][4], accz[4];
#pragma unroll
    for (int nt = 0; nt < 8; nt++)
#pragma unroll
        for (int q = 0; q < 4; q++) acc[nt][q] = 0.f;
#pragma unroll
    for (int q = 0; q < 4; q++) accz[q] = 0.f;

    uint32_t bz[2];
    bz[0] = bz[1] = (lane < 4) ? 0x3C003C00u : 0u;

    uint32_t bAddr = sb + (((lane & 7) + ((lane >> 4) & 1) * 8)) * (BSTR * 2)
                   + ((lane >> 3) & 1) * 16;

    auto stageB = [&](int j0, int bufn) {
        __half* Bd = (__half*)(sm + bufn * BBUF);
#pragma unroll
        for (int q = 0; q < 2; q++) {
            int lin = tid + q * 256;
            int f = lin >> 3, c = lin & 7;
            uint4 v = *(const uint4*)&g_WhT[(head * OF + f) * NN + j0 + c * 8];
            *(uint4*)&Bd[f * BSTR + c * 8] = v;
        }
    };

    // prefetch registers for next step's fragments
    __half2 nJd[8], nJe[8], nJe2[8];
    uint2 nbw0, nbw1;

    auto genLoad = [&](int s1) {
        nbw0 = *(const uint2*)(bitR0 + s1 * 2);
        nbw1 = *(const uint2*)(bitR1 + s1 * 2);
        int base = hpo + (s1 << 5) + t;
#pragma unroll
        for (int kc = 0; kc < 4; kc++) {
            nJd[kc * 2]      = g_pd[base + kc * 8];
            nJd[kc * 2 + 1]  = g_pd[base + kc * 8 + 4];
            nJe[kc * 2]      = g_pe[base + kc * 8];
            nJe[kc * 2 + 1]  = g_pe[base + kc * 8 + 4];
            nJe2[kc * 2]     = g_pe2[base + kc * 8];
            nJe2[kc * 2 + 1] = g_pe2[base + kc * 8 + 4];
        }
    };

    const __half2 zero2 = __float2half2_rn(0.f);
    auto val = [&](int rowIdx, __half2 dst2, __half2 ed, __half2 ed2,
                   unsigned sel) -> uint32_t {
        unsigned g = __hgt2_mask(__hadd2(isrc[rowIdx], dst2), zero2);
        unsigned v = (h2u(__hmul2(ies[rowIdx], ed)) & g)
                   | (h2u(__hmul2(ies2[rowIdx], ed2)) & ~g);
        unsigned mask = (sel & 1u) * 0x0000FFFFu + (sel & 2u) * 0x7FFF8000u;
        return v & mask;
    };

    uint32_t frag[4][4];
    auto genCompute = [&]() {
#pragma unroll
        for (int kc = 0; kc < 4; kc++) {
            unsigned w0 = (kc < 2) ? nbw0.x : nbw0.y;
            unsigned w1 = (kc < 2) ? nbw1.x : nbw1.y;
            int shA = ((kc & 1) << 4) + t2;
            frag[kc][0] = val(0, nJd[kc * 2],     nJe[kc * 2],     nJe2[kc * 2],     (w0 >> shA) & 3u);
            frag[kc][1] = val(1, nJd[kc * 2],     nJe[kc * 2],     nJe2[kc * 2],     (w1 >> shA) & 3u);
            frag[kc][2] = val(0, nJd[kc * 2 + 1], nJe[kc * 2 + 1], nJe2[kc * 2 + 1], (w0 >> (shA + 8)) & 3u);
            frag[kc][3] = val(1, nJd[kc * 2 + 1], nJe[kc * 2 + 1], nJe2[kc * 2 + 1], (w1 >> (shA + 8)) & 3u);
        }
    };

    // prologue
    stageB(0, 0);
    genLoad(0);
    genCompute();        // frag for step 0 (latency exposed once)

    for (int s = 0; s < 64; s++) {
        int buf = s & 1;
        __syncthreads();                 // B buf ready; buf^1 free for writes
        if (s < 63) {
            genLoad(s + 1);              // issue LDGs early; consumed after mma
            stageB((s + 1) << 6, buf ^ 1);
        }

        // mma on current frag + B buffer
#pragma unroll
        for (int kc = 0; kc < 4; kc++) {
            uint32_t b[16];
#pragma unroll
            for (int nq = 0; nq < 4; nq++)
                ldsm4(b[nq * 4], b[nq * 4 + 1], b[nq * 4 + 2], b[nq * 4 + 3],
                      bAddr + buf * BBUF + nq * 16 * (BSTR * 2) + kc * 32);
#pragma unroll
            for (int nt = 0; nt < 8; nt++)
                mma16816(acc[nt], frag[kc], &b[nt * 2]);
            mma16816(accz, frag[kc], bz);
        }

        if (s < 63) genCompute();        // WAR-safe: frag already consumed
    }

    float z0 = __shfl_sync(0xFFFFFFFFu, accz[0], lane & 28);
    float z1 = __shfl_sync(0xFFFFFFFFu, accz[2], lane & 28);
    float inv0 = 1.0f / z0;
    float inv1 = 1.0f / z1;

    {
        float* o0 = out + (size_t)row0 * CF + head * OF + t2;
        float* o1 = o0 + 8 * CF;
#pragma unroll
        for (int nt = 0; nt < 8; nt++) {
            float v0 = acc[nt][0] * inv0, v1 = acc[nt][1] * inv0;
            float v2 = acc[nt][2] * inv1, v3 = acc[nt][3] * inv1;
            v0 = v0 > 0.f ? v0 : (expf(v0) - 1.0f);
            v1 = v1 > 0.f ? v1 : (expf(v1) - 1.0f);
            v2 = v2 > 0.f ? v2 : (expf(v2) - 1.0f);
            v3 = v3 > 0.f ? v3 : (expf(v3) - 1.0f);
            *(float2*)(o0 + nt * 8) = make_float2(v0, v1);
            *(float2*)(o1 + nt * 8) = make_float2(v2, v3);
        }
    }
}

// ============================================================
extern "C" void kernel_launch(void* const* d_in, const int* in_sizes, int n_in,
                              void* d_out, int out_size) {
    const float* h   = (const float*)d_in[0];
    const int*   adj = (const int*)d_in[1];
    const float* W   = (const float*)d_in[2];
    const float* a   = (const float*)d_in[3];
    float* out = (float*)d_out;

    k_nop<<<1, 32>>>();
    k_cvtW<<<dim3(16, 16), 256>>>(W);
    k_ws<<<32, 256>>>(W, a);
    k_gemm16<<<dim3(8, 32), 256>>>(h);
    k_prep<<<NN, 256>>>(adj, h);

    cudaFuncSetAttribute(k_gat_mma, cudaFuncAttributeMaxDynamicSharedMemorySize, SM_TOT);
    k_gat_mma<<<dim3(NH, NN / 128), 256, SM_TOT>>>(out);
}

// round 14
// speedup vs baseline: 1.4137x; 1.0446x over previous
#include <cuda_runtime.h>
#include <cuda_fp16.h>
#include <math.h>
#include <stdint.h>

#define NN   4096
#define KF   512     // IN_F
#define CF   512     // OUT_F * N_HEADS
#define NH   8
#define OF   64

// ---- scratch (device globals; no allocation allowed) ----
__device__ __half   g_W16T[CF * KF];          // 512 KB  W fp16 transposed [c][k]
__device__ float    g_wst[16 * KF];           // 32 KB   ws_t[h*2+d][k]
__device__ __half   g_Whf16[(size_t)NN * CF]; // 4 MB    Wh fp16 [n][c]
__device__ __half   g_WhT[NH * OF * NN];      // 4 MB    values transposed [h][f][n]
__device__ unsigned g_bits[NN * 128];         // 2 MB    packed adj
__device__ float4   g_attrS[NH * NN];         // (src, Es/16, Es2/16, 0)
__device__ __half2  g_pd[NH * (NN / 2)];      // per j-pair dst2
__device__ __half2  g_pe[NH * (NN / 2)];      // per j-pair Ed2
__device__ __half2  g_pe2[NH * (NN / 2)];     // per j-pair Ed2^0.2

__device__ __forceinline__ uint32_t smem_u32(const void* p) {
    uint32_t a;
    asm("{ .reg .u64 t; cvta.to.shared.u64 t, %1; cvt.u32.u64 %0, t; }" : "=r"(a) : "l"(p));
    return a;
}
__device__ __forceinline__ unsigned h2u(__half2 v) {
    return *reinterpret_cast<unsigned*>(&v);
}
__device__ __forceinline__ void ldsm4(uint32_t& r0, uint32_t& r1, uint32_t& r2, uint32_t& r3,
                                      uint32_t addr) {
    asm volatile("ldmatrix.sync.aligned.m8n8.x4.shared.b16 {%0,%1,%2,%3}, [%4];"
                 : "=r"(r0), "=r"(r1), "=r"(r2), "=r"(r3) : "r"(addr));
}
__device__ __forceinline__ void mma16816(float* d, const uint32_t* a, const uint32_t* b) {
    asm volatile(
        "mma.sync.aligned.m16n8k16.row.col.f32.f16.f16.f32 "
        "{%0,%1,%2,%3}, {%4,%5,%6,%7}, {%8,%9}, {%0,%1,%2,%3};"
        : "+f"(d[0]), "+f"(d[1]), "+f"(d[2]), "+f"(d[3])
        : "r"(a[0]), "r"(a[1]), "r"(a[2]), "r"(a[3]), "r"(b[0]), "r"(b[1]));
}
#define CP_ASYNC16(smem, gmem) \
    asm volatile("cp.async.cg.shared.global [%0], [%1], 16;" :: "r"(smem), "l"(gmem) : "memory")
#define CP_COMMIT() asm volatile("cp.async.commit_group;" ::: "memory")
#define CP_WAIT2()  asm volatile("cp.async.wait_group 2;" ::: "memory")

// ============================================================
__global__ void k_nop() {}   // ncu launch-index shim

// ============================================================
// W -> W16T (fp16, transposed [c][k])
// ============================================================
__global__ __launch_bounds__(256) void k_cvtW(const float* __restrict__ W) {
    __shared__ float Ts[32][33];
    int k0 = blockIdx.y * 32, c0 = blockIdx.x * 32;
    int tx = threadIdx.x & 31, ty = threadIdx.x >> 5;
#pragma unroll
    for (int q = 0; q < 4; q++) {
        int r = ty + q * 8;
        Ts[r][tx] = W[(k0 + r) * CF + c0 + tx];
    }
    __syncthreads();
#pragma unroll
    for (int q = 0; q < 4; q++) {
        int cy = ty + q * 8;
        g_W16T[(c0 + cy) * KF + k0 + tx] = __float2half(Ts[tx][cy]);
    }
}

// ============================================================
// ws_t[hd][k] = sum_f W[k][h*64+f] * a[d*64+f]  (exact fp32)
// ============================================================
__global__ __launch_bounds__(256) void k_ws(const float* __restrict__ W,
                                            const float* __restrict__ a) {
    __shared__ float as[128];
    if (threadIdx.x < 128) as[threadIdx.x] = a[threadIdx.x];
    __syncthreads();
    int idx = blockIdx.x * 256 + threadIdx.x;
    int hd = idx & 15, k = idx >> 4;
    int h = hd >> 1, d = hd & 1;
    const float* wr = W + k * CF + h * OF;
    const float* av = as + d * OF;
    float s = 0.f;
#pragma unroll 16
    for (int f = 0; f < OF; f++) s += wr[f] * av[f];
    g_wst[hd * KF + k] = s;
}

// ============================================================
// Whf16 = h @ W via HMMA
// ============================================================
#define GASTR 72
#define GBSTR 72
__global__ __launch_bounds__(256) void k_gemm16(const float* __restrict__ h) {
    __shared__ __half As[128 * GASTR];
    __shared__ __half Bs[64 * GBSTR];
    int tid = threadIdx.x, wid = tid >> 5, lane = tid & 31;
    int n0 = blockIdx.y * 128, c0 = blockIdx.x * 64;
    float acc[8][4];
#pragma unroll
    for (int nt = 0; nt < 8; nt++)
#pragma unroll
        for (int q = 0; q < 4; q++) acc[nt][q] = 0.f;
    uint32_t aAddr = smem_u32(As) + (wid * 16 + (lane & 15)) * (GASTR * 2) + (lane >> 4) * 16;
    uint32_t bAddr = smem_u32(Bs) + (((lane & 7) + ((lane >> 4) & 1) * 8)) * (GBSTR * 2)
                   + ((lane >> 3) & 1) * 16;

    for (int k0 = 0; k0 < KF; k0 += 64) {
        __syncthreads();
#pragma unroll
        for (int q = 0; q < 8; q++) {
            int lin = tid + q * 256;
            int rr = lin >> 4, kq = (lin & 15) * 4;
            float4 v = *(const float4*)(h + (size_t)(n0 + rr) * KF + k0 + kq);
            *(__half2*)&As[rr * GASTR + kq]     = __floats2half2_rn(v.x, v.y);
            *(__half2*)&As[rr * GASTR + kq + 2] = __floats2half2_rn(v.z, v.w);
        }
#pragma unroll
        for (int q = 0; q < 2; q++) {
            int lin = tid + q * 256;
            int cc = lin >> 3, kq = (lin & 7) * 8;
            uint4 v = *(const uint4*)&g_W16T[(c0 + cc) * KF + k0 + kq];
            *(uint4*)&Bs[cc * GBSTR + kq] = v;
        }
        __syncthreads();
#pragma unroll
        for (int kc = 0; kc < 4; kc++) {
            uint32_t aa[4];
            ldsm4(aa[0], aa[1], aa[2], aa[3], aAddr + kc * 32);
            uint32_t b[16];
#pragma unroll
            for (int nq = 0; nq < 4; nq++)
                ldsm4(b[nq * 4], b[nq * 4 + 1], b[nq * 4 + 2], b[nq * 4 + 3],
                      bAddr + nq * 16 * (GBSTR * 2) + kc * 32);
#pragma unroll
            for (int nt = 0; nt < 8; nt++) mma16816(acc[nt], aa, &b[nt * 2]);
        }
    }
    int r0 = n0 + wid * 16 + (lane >> 2);
    int cb = c0 + (lane & 3) * 2;
#pragma unroll
    for (int nt = 0; nt < 8; nt++) {
        *(__half2*)&g_Whf16[(size_t)r0 * CF + cb + nt * 8] =
            __floats2half2_rn(acc[nt][0], acc[nt][1]);
        *(__half2*)&g_Whf16[(size_t)(r0 + 8) * CF + cb + nt * 8] =
            __floats2half2_rn(acc[nt][2], acc[nt][3]);
    }
}

// ============================================================
// PREP: pack adj bits; attrs via h @ ws_t (exact);
// transpose Whf16 -> WhT (blocks 0..255)
// ============================================================
__global__ __launch_bounds__(256) void k_prep(const int* __restrict__ adj,
                                              const float* __restrict__ hsrc) {
    __shared__ __half Ts[64 * 130];
    int b = blockIdx.x, tid = threadIdx.x;
    int w = tid >> 5, lane = tid & 31;

    // pack adj row b
#pragma unroll
    for (int q = 0; q < 16; q++) {
        int wd = w * 16 + q;
        int j = wd * 32 + lane;
        unsigned bt = __ballot_sync(0xFFFFFFFFu, adj[(size_t)b * NN + j] > 0);
        if (lane == 0) g_bits[b * 128 + wd] = bt;
    }

    // attrs: (node b, head w), exact fp32 via ws_t
    {
        const float* hr  = hsrc + (size_t)b * KF;
        const float* wsS = g_wst + (2 * w) * KF;
        const float* wsD = g_wst + (2 * w + 1) * KF;
        float s = 0.f, d = 0.f;
#pragma unroll
        for (int t = 0; t < 16; t++) {
            float hv = hr[lane + 32 * t];
            s += hv * wsS[lane + 32 * t];
            d += hv * wsD[lane + 32 * t];
        }
#pragma unroll
        for (int o = 16; o; o >>= 1) {
            s += __shfl_xor_sync(0xFFFFFFFFu, s, o);
            d += __shfl_xor_sync(0xFFFFFFFFu, d, o);
        }
        if (lane == 0) {
            g_attrS[w * NN + b] = make_float4(s, expf(s) * 0.0625f, expf(0.2f * s) * 0.0625f, 0.f);
            int pi = w * (NN / 2) + (b >> 1);
            ((__half*)&g_pd[pi])[b & 1]  = __float2half(d);
            ((__half*)&g_pe[pi])[b & 1]  = __float2half(expf(d));
            ((__half*)&g_pe2[pi])[b & 1] = __float2half(expf(0.2f * d));
        }
    }

    // transpose (blocks 0..255)
    if (b < 256) {
        int hh = b & 7, n0 = (b >> 3) * 128;
        __syncthreads();
#pragma unroll
        for (int q = 0; q < 32; q++) {
            int lin = tid + q * 256;
            int r = lin >> 6, c = lin & 63;
            Ts[c * 130 + r] = g_Whf16[(size_t)(n0 + r) * CF + hh * OF + c];
        }
        __syncthreads();
#pragma unroll
        for (int q = 0; q < 16; q++) {
            int lin = tid + q * 256;
            int f = lin >> 6, n2 = lin & 63;
            __half2 hv = __halves2half2(Ts[f * 130 + n2 * 2], Ts[f * 130 + n2 * 2 + 1]);
            *(__half2*)&g_WhT[(hh * OF + f) * NN + n0 + n2 * 2] = hv;
        }
    }
}

// ============================================================
// GAT: register A-fragments (split load/compute prefetch),
// B staged via cp.async 4-stage pipeline, 2 CTAs/SM
// ============================================================
#define BSTR 72
#define BBUF 9216                       // 64*72*2
#define SM_TOT (4 * BBUF + 128)

__global__ __launch_bounds__(256, 2) void k_gat_mma(float* __restrict__ out) {
    extern __shared__ char sm[];
    uint32_t sb = smem_u32(sm);

    int tid = threadIdx.x, wid = tid >> 5, lane = tid & 31;
    int head = blockIdx.x, i0 = blockIdx.y << 7;
    int r = lane >> 2, t = lane & 3;
    int t2 = t << 1;

    int row0 = i0 + wid * 16 + r;
    __half2 isrc[2], ies[2], ies2[2];
    {
        float4 v0 = g_attrS[head * NN + row0];
        float4 v1 = g_attrS[head * NN + row0 + 8];
        isrc[0] = __float2half2_rn(v0.x); ies[0] = __float2half2_rn(v0.y);
        ies2[0] = __float2half2_rn(v0.z);
        isrc[1] = __float2half2_rn(v1.x); ies[1] = __float2half2_rn(v1.y);
        ies2[1] = __float2half2_rn(v1.z);
    }
    const unsigned* bitR0 = g_bits + (size_t)row0 * 128;
    const unsigned* bitR1 = bitR0 + 8 * 128;
    const int hpo = head * (NN / 2);

    float acc[8][4], accz[4];
#pragma unroll
    for (int nt = 0; nt < 8; nt++)
#pragma unroll
        for (int q = 0; q < 4; q++) acc[nt][q] = 0.f;
#pragma unroll
    for (int q = 0; q < 4; q++) accz[q] = 0.f;

    uint32_t bz[2];
    bz[0] = bz[1] = (lane < 4) ? 0x3C003C00u : 0u;

    uint32_t bAddr = sb + (((lane & 7) + ((lane >> 4) & 1) * 8)) * (BSTR * 2)
                   + ((lane >> 3) & 1) * 16;

    // async B staging: data flows GMEM->SMEM directly
    auto stageB = [&](int j0, int bufn) {
#pragma unroll
        for (int q = 0; q < 2; q++) {
            int lin = tid + q * 256;
            int f = lin >> 3, c = lin & 7;
            const __half* gp = &g_WhT[(head * OF + f) * NN + j0 + c * 8];
            uint32_t sp = sb + bufn * BBUF + (uint32_t)(f * BSTR + c * 8) * 2;
            CP_ASYNC16(sp, gp);
        }
    };

    // prefetch registers for next step's fragments
    __half2 nJd[8], nJe[8], nJe2[8];
    uint2 nbw0, nbw1;

    auto genLoad = [&](int s1) {
        nbw0 = *(const uint2*)(bitR0 + s1 * 2);
        nbw1 = *(const uint2*)(bitR1 + s1 * 2);
        int base = hpo + (s1 << 5) + t;
#pragma unroll
        for (int kc = 0; kc < 4; kc++) {
            nJd[kc * 2]      = g_pd[base + kc * 8];
            nJd[kc * 2 + 1]  = g_pd[base + kc * 8 + 4];
            nJe[kc * 2]      = g_pe[base + kc * 8];
            nJe[kc * 2 + 1]  = g_pe[base + kc * 8 + 4];
            nJe2[kc * 2]     = g_pe2[base + kc * 8];
            nJe2[kc * 2 + 1] = g_pe2[base + kc * 8 + 4];
        }
    };

    const __half2 zero2 = __float2half2_rn(0.f);
    auto val = [&](int rowIdx, __half2 dst2, __half2 ed, __half2 ed2,
                   unsigned sel) -> uint32_t {
        unsigned g = __hgt2_mask(__hadd2(isrc[rowIdx], dst2), zero2);
        unsigned v = (h2u(__hmul2(ies[rowIdx], ed)) & g)
                   | (h2u(__hmul2(ies2[rowIdx], ed2)) & ~g);
        unsigned mask = (sel & 1u) * 0x0000FFFFu + (sel & 2u) * 0x7FFF8000u;
        return v & mask;
    };

    uint32_t frag[4][4];
    auto genCompute = [&]() {
#pragma unroll
        for (int kc = 0; kc < 4; kc++) {
            unsigned w0 = (kc < 2) ? nbw0.x : nbw0.y;
            unsigned w1 = (kc < 2) ? nbw1.x : nbw1.y;
            int shA = ((kc & 1) << 4) + t2;
            frag[kc][0] = val(0, nJd[kc * 2],     nJe[kc * 2],     nJe2[kc * 2],     (w0 >> shA) & 3u);
            frag[kc][1] = val(1, nJd[kc * 2],     nJe[kc * 2],     nJe2[kc * 2],     (w1 >> shA) & 3u);
            frag[kc][2] = val(0, nJd[kc * 2 + 1], nJe[kc * 2 + 1], nJe2[kc * 2 + 1], (w0 >> (shA + 8)) & 3u);
            frag[kc][3] = val(1, nJd[kc * 2 + 1], nJe[kc * 2 + 1], nJe2[kc * 2 + 1], (w1 >> (shA + 8)) & 3u);
        }
    };

    // prologue: prime 3 pipeline stages + first fragments
    stageB(0, 0);   CP_COMMIT();
    stageB(64, 1);  CP_COMMIT();
    stageB(128, 2); CP_COMMIT();
    genLoad(0);
    genCompute();

    for (int s = 0; s < 64; s++) {
        CP_WAIT2();                      // stage s complete (this thread)
        __syncthreads();                 // all threads' stage s visible; prior mma done
        if (s < 63) genLoad(s + 1);      // early LDGs for next fragments
        if (s + 3 < 64) stageB((s + 3) << 6, (s + 3) & 3);
        CP_COMMIT();                     // unconditional: keeps group accounting exact

        int buf = s & 3;
#pragma unroll
        for (int kc = 0; kc < 4; kc++) {
            uint32_t b[16];
#pragma unroll
            for (int nq = 0; nq < 4; nq++)
                ldsm4(b[nq * 4], b[nq * 4 + 1], b[nq * 4 + 2], b[nq * 4 + 3],
                      bAddr + buf * BBUF + nq * 16 * (BSTR * 2) + kc * 32);
#pragma unroll
            for (int nt = 0; nt < 8; nt++)
                mma16816(acc[nt], frag[kc], &b[nt * 2]);
            mma16816(accz, frag[kc], bz);
        }

        if (s < 63) genCompute();        // WAR-safe: frag consumed above
    }

    float z0 = __shfl_sync(0xFFFFFFFFu, accz[0], lane & 28);
    float z1 = __shfl_sync(0xFFFFFFFFu, accz[2], lane & 28);
    float inv0 = 1.0f / z0;
    float inv1 = 1.0f / z1;

    {
        float* o0 = out + (size_t)row0 * CF + head * OF + t2;
        float* o1 = o0 + 8 * CF;
#pragma unroll
        for (int nt = 0; nt < 8; nt++) {
            float v0 = acc[nt][0] * inv0, v1 = acc[nt][1] * inv0;
            float v2 = acc[nt][2] * inv1, v3 = acc[nt][3] * inv1;
            v0 = v0 > 0.f ? v0 : (expf(v0) - 1.0f);
            v1 = v1 > 0.f ? v1 : (expf(v1) - 1.0f);
            v2 = v2 > 0.f ? v2 : (expf(v2) - 1.0f);
            v3 = v3 > 0.f ? v3 : (expf(v3) - 1.0f);
            *(float2*)(o0 + nt * 8) = make_float2(v0, v1);
            *(float2*)(o1 + nt * 8) = make_float2(v2, v3);
        }
    }
}

// ============================================================
extern "C" void kernel_launch(void* const* d_in, const int* in_sizes, int n_in,
                              void* d_out, int out_size) {
    const float* h   = (const float*)d_in[0];
    const int*   adj = (const int*)d_in[1];
    const float* W   = (const float*)d_in[2];
    const float* a   = (const float*)d_in[3];
    float* out = (float*)d_out;

    k_nop<<<1, 32>>>();
    k_cvtW<<<dim3(16, 16), 256>>>(W);
    k_ws<<<32, 256>>>(W, a);
    k_gemm16<<<dim3(8, 32), 256>>>(h);
    k_prep<<<NN, 256>>>(adj, h);

    cudaFuncSetAttribute(k_gat_mma, cudaFuncAttributeMaxDynamicSharedMemorySize, SM_TOT);
    k_gat_mma<<<dim3(NH, NN / 128), 256, SM_TOT>>>(out);
}

// round 15
// speedup vs baseline: 1.4797x; 1.0467x over previous
#include <cuda_runtime.h>
#include <cuda_fp16.h>
#include <math.h>
#include <stdint.h>

#define NN   4096
#define KF   512     // IN_F
#define CF   512     // OUT_F * N_HEADS
#define NH   8
#define OF   64

// ---- scratch (device globals; no allocation allowed) ----
__device__ __half   g_W16T[CF * KF];          // 512 KB  W fp16 transposed [c][k]
__device__ float    g_wst[16 * KF];           // 32 KB   ws_t[h*2+d][k]
__device__ __half   g_Whf16[(size_t)NN * CF]; // 4 MB    Wh fp16 [n][c]
__device__ __half   g_WhT[NH * OF * NN];      // 4 MB    values transposed [h][f][n]
__device__ unsigned g_bits[NN * 128];         // 2 MB    packed adj
__device__ float4   g_attrS[NH * NN];         // (src, Es/16, Es2/16, 0)
__device__ __half2  g_pd[NH * (NN / 2)];      // per j-pair dst2
__device__ __half2  g_pe[NH * (NN / 2)];      // per j-pair Ed2
__device__ __half2  g_pe2[NH * (NN / 2)];     // per j-pair Ed2^0.2

__device__ __forceinline__ uint32_t smem_u32(const void* p) {
    uint32_t a;
    asm("{ .reg .u64 t; cvta.to.shared.u64 t, %1; cvt.u32.u64 %0, t; }" : "=r"(a) : "l"(p));
    return a;
}
__device__ __forceinline__ unsigned h2u(__half2 v) {
    return *reinterpret_cast<unsigned*>(&v);
}
__device__ __forceinline__ void ldsm4(uint32_t& r0, uint32_t& r1, uint32_t& r2, uint32_t& r3,
                                      uint32_t addr) {
    asm volatile("ldmatrix.sync.aligned.m8n8.x4.shared.b16 {%0,%1,%2,%3}, [%4];"
                 : "=r"(r0), "=r"(r1), "=r"(r2), "=r"(r3) : "r"(addr));
}
__device__ __forceinline__ void mma16816(float* d, const uint32_t* a, const uint32_t* b) {
    asm volatile(
        "mma.sync.aligned.m16n8k16.row.col.f32.f16.f16.f32 "
        "{%0,%1,%2,%3}, {%4,%5,%6,%7}, {%8,%9}, {%0,%1,%2,%3};"
        : "+f"(d[0]), "+f"(d[1]), "+f"(d[2]), "+f"(d[3])
        : "r"(a[0]), "r"(a[1]), "r"(a[2]), "r"(a[3]), "r"(b[0]), "r"(b[1]));
}
#define CP_ASYNC16(smem, gmem) \
    asm volatile("cp.async.cg.shared.global [%0], [%1], 16;" :: "r"(smem), "l"(gmem) : "memory")
#define CP_COMMIT() asm volatile("cp.async.commit_group;" ::: "memory")
#define CP_WAIT2()  asm volatile("cp.async.wait_group 2;" ::: "memory")

// ============================================================
// K1: cvtW (blocks 0..255) + ws (blocks 256..287)
// ============================================================
__global__ __launch_bounds__(256) void k_wprep(const float* __restrict__ W,
                                               const float* __restrict__ a) {
    __shared__ float Ts[32][33];
    int b = blockIdx.x, tid = threadIdx.x;
    if (b < 256) {
        int k0 = (b >> 4) * 32, c0 = (b & 15) * 32;
        int tx = tid & 31, ty = tid >> 5;
#pragma unroll
        for (int q = 0; q < 4; q++) {
            int r = ty + q * 8;
            Ts[r][tx] = W[(k0 + r) * CF + c0 + tx];
        }
        __syncthreads();
#pragma unroll
        for (int q = 0; q < 4; q++) {
            int cy = ty + q * 8;
            g_W16T[(c0 + cy) * KF + k0 + tx] = __float2half(Ts[tx][cy]);
        }
    } else {
        __shared__ float as[128];
        if (tid < 128) as[tid] = a[tid];
        __syncthreads();
        int idx = (b - 256) * 256 + tid;          // 8192 total
        int hd = idx & 15, k = idx >> 4;
        int h = hd >> 1, d = hd & 1;
        const float* wr = W + k * CF + h * OF;
        const float* av = as + d * OF;
        float s = 0.f;
#pragma unroll 16
        for (int f = 0; f < OF; f++) s += wr[f] * av[f];
        g_wst[hd * KF + k] = s;
    }
}

// ============================================================
// K2: gemm16 (blocks 0..255) + adj-pack/attrs (blocks 256..4351)
// ============================================================
#define GASTR 72
#define GBSTR 72
__global__ __launch_bounds__(256) void k_big(const float* __restrict__ h,
                                             const int* __restrict__ adj) {
    __shared__ __half sm2[128 * GASTR + 64 * GBSTR];
    int bidx = blockIdx.x, tid = threadIdx.x;

    if (bidx < 256) {
        // ---------------- gemm16 ----------------
        __half* As = sm2;
        __half* Bs = sm2 + 128 * GASTR;
        int wid = tid >> 5, lane = tid & 31;
        int c0 = (bidx & 7) * 64, n0 = (bidx >> 3) * 128;
        float acc[8][4];
#pragma unroll
        for (int nt = 0; nt < 8; nt++)
#pragma unroll
            for (int q = 0; q < 4; q++) acc[nt][q] = 0.f;
        uint32_t aAddr = smem_u32(As) + (wid * 16 + (lane & 15)) * (GASTR * 2) + (lane >> 4) * 16;
        uint32_t bAddr = smem_u32(Bs) + (((lane & 7) + ((lane >> 4) & 1) * 8)) * (GBSTR * 2)
                       + ((lane >> 3) & 1) * 16;

        for (int k0 = 0; k0 < KF; k0 += 64) {
            __syncthreads();
#pragma unroll
            for (int q = 0; q < 8; q++) {
                int lin = tid + q * 256;
                int rr = lin >> 4, kq = (lin & 15) * 4;
                float4 v = *(const float4*)(h + (size_t)(n0 + rr) * KF + k0 + kq);
                *(__half2*)&As[rr * GASTR + kq]     = __floats2half2_rn(v.x, v.y);
                *(__half2*)&As[rr * GASTR + kq + 2] = __floats2half2_rn(v.z, v.w);
            }
#pragma unroll
            for (int q = 0; q < 2; q++) {
                int lin = tid + q * 256;
                int cc = lin >> 3, kq = (lin & 7) * 8;
                uint4 v = *(const uint4*)&g_W16T[(c0 + cc) * KF + k0 + kq];
                *(uint4*)&Bs[cc * GBSTR + kq] = v;
            }
            __syncthreads();
#pragma unroll
            for (int kc = 0; kc < 4; kc++) {
                uint32_t aa[4];
                ldsm4(aa[0], aa[1], aa[2], aa[3], aAddr + kc * 32);
                uint32_t b[16];
#pragma unroll
                for (int nq = 0; nq < 4; nq++)
                    ldsm4(b[nq * 4], b[nq * 4 + 1], b[nq * 4 + 2], b[nq * 4 + 3],
                          bAddr + nq * 16 * (GBSTR * 2) + kc * 32);
#pragma unroll
                for (int nt = 0; nt < 8; nt++) mma16816(acc[nt], aa, &b[nt * 2]);
            }
        }
        int r0 = n0 + wid * 16 + (lane >> 2);
        int cb = c0 + (lane & 3) * 2;
#pragma unroll
        for (int nt = 0; nt < 8; nt++) {
            *(__half2*)&g_Whf16[(size_t)r0 * CF + cb + nt * 8] =
                __floats2half2_rn(acc[nt][0], acc[nt][1]);
            *(__half2*)&g_Whf16[(size_t)(r0 + 8) * CF + cb + nt * 8] =
                __floats2half2_rn(acc[nt][2], acc[nt][3]);
        }
    } else {
        // ---------------- adj pack + attrs, node b ----------------
        int b = bidx - 256;
        int w = tid >> 5, lane = tid & 31;
#pragma unroll
        for (int q = 0; q < 16; q++) {
            int wd = w * 16 + q;
            int j = wd * 32 + lane;
            unsigned bt = __ballot_sync(0xFFFFFFFFu, adj[(size_t)b * NN + j] > 0);
            if (lane == 0) g_bits[b * 128 + wd] = bt;
        }
        {
            const float* hr  = h + (size_t)b * KF;
            const float* wsS = g_wst + (2 * w) * KF;
            const float* wsD = g_wst + (2 * w + 1) * KF;
            float s = 0.f, d = 0.f;
#pragma unroll
            for (int t = 0; t < 16; t++) {
                float hv = hr[lane + 32 * t];
                s += hv * wsS[lane + 32 * t];
                d += hv * wsD[lane + 32 * t];
            }
#pragma unroll
            for (int o = 16; o; o >>= 1) {
                s += __shfl_xor_sync(0xFFFFFFFFu, s, o);
                d += __shfl_xor_sync(0xFFFFFFFFu, d, o);
            }
            if (lane == 0) {
                g_attrS[w * NN + b] = make_float4(s, expf(s) * 0.0625f,
                                                  expf(0.2f * s) * 0.0625f, 0.f);
                int pi = w * (NN / 2) + (b >> 1);
                ((__half*)&g_pd[pi])[b & 1]  = __float2half(d);
                ((__half*)&g_pe[pi])[b & 1]  = __float2half(expf(d));
                ((__half*)&g_pe2[pi])[b & 1] = __float2half(expf(0.2f * d));
            }
        }
    }
}

// ============================================================
// K3: transpose Whf16 -> WhT, 256 blocks
// ============================================================
__global__ __launch_bounds__(256) void k_tr() {
    __shared__ __half Ts[64 * 130];
    int b = blockIdx.x, tid = threadIdx.x;
    int hh = b & 7, n0 = (b >> 3) * 128;
#pragma unroll
    for (int q = 0; q < 32; q++) {
        int lin = tid + q * 256;
        int r = lin >> 6, c = lin & 63;
        Ts[c * 130 + r] = g_Whf16[(size_t)(n0 + r) * CF + hh * OF + c];
    }
    __syncthreads();
#pragma unroll
    for (int q = 0; q < 16; q++) {
        int lin = tid + q * 256;
        int f = lin >> 6, n2 = lin & 63;
        __half2 hv = __halves2half2(Ts[f * 130 + n2 * 2], Ts[f * 130 + n2 * 2 + 1]);
        *(__half2*)&g_WhT[(hh * OF + f) * NN + n0 + n2 * 2] = hv;
    }
}

// ============================================================
// GAT: register A-fragments (split load/compute prefetch),
// B staged via cp.async 4-stage pipeline, 2 CTAs/SM
// ============================================================
#define BSTR 72
#define BBUF 9216                       // 64*72*2
#define SM_TOT (4 * BBUF + 128)

__global__ __launch_bounds__(256, 2) void k_gat_mma(float* __restrict__ out) {
    extern __shared__ char sm[];
    uint32_t sb = smem_u32(sm);

    int tid = threadIdx.x, wid = tid >> 5, lane = tid & 31;
    int head = blockIdx.x, i0 = blockIdx.y << 7;
    int r = lane >> 2, t = lane & 3;
    int t2 = t << 1;

    int row0 = i0 + wid * 16 + r;
    __half2 isrc[2], ies[2], ies2[2];
    {
        float4 v0 = g_attrS[head * NN + row0];
        float4 v1 = g_attrS[head * NN + row0 + 8];
        isrc[0] = __float2half2_rn(v0.x); ies[0] = __float2half2_rn(v0.y);
        ies2[0] = __float2half2_rn(v0.z);
        isrc[1] = __float2half2_rn(v1.x); ies[1] = __float2half2_rn(v1.y);
        ies2[1] = __float2half2_rn(v1.z);
    }
    const unsigned* bitR0 = g_bits + (size_t)row0 * 128;
    const unsigned* bitR1 = bitR0 + 8 * 128;
    const int hpo = head * (NN / 2);

    float acc[8][4], accz[4];
#pragma unroll
    for (int nt = 0; nt < 8; nt++)
#pragma unroll
        for (int q = 0; q < 4; q++) acc[nt][q] = 0.f;
#pragma unroll
    for (int q = 0; q < 4; q++) accz[q] = 0.f;

    uint32_t bz[2];
    bz[0] = bz[1] = (lane < 4) ? 0x3C003C00u : 0u;

    uint32_t bAddr = sb + (((lane & 7) + ((lane >> 4) & 1) * 8)) * (BSTR * 2)
                   + ((lane >> 3) & 1) * 16;

    auto stageB = [&](int j0, int bufn) {
#pragma unroll
        for (int q = 0; q < 2; q++) {
            int lin = tid + q * 256;
            int f = lin >> 3, c = lin & 7;
            const __half* gp = &g_WhT[(head * OF + f) * NN + j0 + c * 8];
            uint32_t sp = sb + bufn * BBUF + (uint32_t)(f * BSTR + c * 8) * 2;
            CP_ASYNC16(sp, gp);
        }
    };

    __half2 nJd[8], nJe[8], nJe2[8];
    uint2 nbw0, nbw1;

    auto genLoad = [&](int s1) {
        nbw0 = *(const uint2*)(bitR0 + s1 * 2);
        nbw1 = *(const uint2*)(bitR1 + s1 * 2);
        int base = hpo + (s1 << 5) + t;
#pragma unroll
        for (int kc = 0; kc < 4; kc++) {
            nJd[kc * 2]      = g_pd[base + kc * 8];
            nJd[kc * 2 + 1]  = g_pd[base + kc * 8 + 4];
            nJe[kc * 2]      = g_pe[base + kc * 8];
            nJe[kc * 2 + 1]  = g_pe[base + kc * 8 + 4];
            nJe2[kc * 2]     = g_pe2[base + kc * 8];
            nJe2[kc * 2 + 1] = g_pe2[base + kc * 8 + 4];
        }
    };

    const __half2 zero2 = __float2half2_rn(0.f);
    auto val = [&](int rowIdx, __half2 dst2, __half2 ed, __half2 ed2,
                   unsigned sel) -> uint32_t {
        unsigned g = __hgt2_mask(__hadd2(isrc[rowIdx], dst2), zero2);
        unsigned v = (h2u(__hmul2(ies[rowIdx], ed)) & g)
                   | (h2u(__hmul2(ies2[rowIdx], ed2)) & ~g);
        unsigned mask = (sel & 1u) * 0x0000FFFFu + (sel & 2u) * 0x7FFF8000u;
        return v & mask;
    };

    uint32_t frag[4][4];
    auto genCompute = [&]() {
#pragma unroll
        for (int kc = 0; kc < 4; kc++) {
            unsigned w0 = (kc < 2) ? nbw0.x : nbw0.y;
            unsigned w1 = (kc < 2) ? nbw1.x : nbw1.y;
            int shA = ((kc & 1) << 4) + t2;
            frag[kc][0] = val(0, nJd[kc * 2],     nJe[kc * 2],     nJe2[kc * 2],     (w0 >> shA) & 3u);
            frag[kc][1] = val(1, nJd[kc * 2],     nJe[kc * 2],     nJe2[kc * 2],     (w1 >> shA) & 3u);
            frag[kc][2] = val(0, nJd[kc * 2 + 1], nJe[kc * 2 + 1], nJe2[kc * 2 + 1], (w0 >> (shA + 8)) & 3u);
            frag[kc][3] = val(1, nJd[kc * 2 + 1], nJe[kc * 2 + 1], nJe2[kc * 2 + 1], (w1 >> (shA + 8)) & 3u);
        }
    };

    stageB(0, 0);   CP_COMMIT();
    stageB(64, 1);  CP_COMMIT();
    stageB(128, 2); CP_COMMIT();
    genLoad(0);
    genCompute();

    for (int s = 0; s < 64; s++) {
        CP_WAIT2();
        __syncthreads();
        if (s < 63) genLoad(s + 1);
        if (s + 3 < 64) stageB((s + 3) << 6, (s + 3) & 3);
        CP_COMMIT();

        int buf = s & 3;
#pragma unroll
        for (int kc = 0; kc < 4; kc++) {
            uint32_t b[16];
#pragma unroll
            for (int nq = 0; nq < 4; nq++)
                ldsm4(b[nq * 4], b[nq * 4 + 1], b[nq * 4 + 2], b[nq * 4 + 3],
                      bAddr + buf * BBUF + nq * 16 * (BSTR * 2) + kc * 32);
#pragma unroll
            for (int nt = 0; nt < 8; nt++)
                mma16816(acc[nt], frag[kc], &b[nt * 2]);
            mma16816(accz, frag[kc], bz);
        }

        if (s < 63) genCompute();
    }

    float z0 = __shfl_sync(0xFFFFFFFFu, accz[0], lane & 28);
    float z1 = __shfl_sync(0xFFFFFFFFu, accz[2], lane & 28);
    float inv0 = 1.0f / z0;
    float inv1 = 1.0f / z1;

    {
        float* o0 = out + (size_t)row0 * CF + head * OF + t2;
        float* o1 = o0 + 8 * CF;
#pragma unroll
        for (int nt = 0; nt < 8; nt++) {
            float v0 = acc[nt][0] * inv0, v1 = acc[nt][1] * inv0;
            float v2 = acc[nt][2] * inv1, v3 = acc[nt][3] * inv1;
            v0 = v0 > 0.f ? v0 : (expf(v0) - 1.0f);
            v1 = v1 > 0.f ? v1 : (expf(v1) - 1.0f);
            v2 = v2 > 0.f ? v2 : (expf(v2) - 1.0f);
            v3 = v3 > 0.f ? v3 : (expf(v3) - 1.0f);
            *(float2*)(o0 + nt * 8) = make_float2(v0, v1);
            *(float2*)(o1 + nt * 8) = make_float2(v2, v3);
        }
    }
}

// ============================================================
extern "C" void kernel_launch(void* const* d_in, const int* in_sizes, int n_in,
                              void* d_out, int out_size) {
    const float* h   = (const float*)d_in[0];
    const int*   adj = (const int*)d_in[1];
    const float* W   = (const float*)d_in[2];
    const float* a   = (const float*)d_in[3];
    float* out = (float*)d_out;

    k_wprep<<<288, 256>>>(W, a);          // cvtW + ws
    k_big<<<4352, 256>>>(h, adj);         // gemm16 + adj pack + attrs
    k_tr<<<256, 256>>>();                 // Whf16 -> WhT

    cudaFuncSetAttribute(k_gat_mma, cudaFuncAttributeMaxDynamicSharedMemorySize, SM_TOT);
    k_gat_mma<<<dim3(NH, NN / 128), 256, SM_TOT>>>(out);   // launch #4 -> ncu capture
}

// round 16
// speedup vs baseline: 1.5242x; 1.0301x over previous
#include <cuda_runtime.h>
#include <cuda_fp16.h>
#include <math.h>
#include <stdint.h>

#define NN   4096
#define KF   512     // IN_F
#define CF   512     // OUT_F * N_HEADS
#define NH   8
#define OF   64

// ---- scratch (device globals; no allocation allowed) ----
__device__ __half   g_W16T[CF * KF];          // 512 KB  W fp16 transposed [c][k]
__device__ float    g_wst[16 * KF];           // 32 KB   ws_t[h*2+d][k]
__device__ __half   g_WhT[NH * OF * NN];      // 4 MB    values transposed [h][f][n]
__device__ unsigned g_bits[NN * 128];         // 2 MB    packed adj
__device__ float4   g_attrS[NH * NN];         // (src, Es/16, Es2/16, 0)
__device__ __half2  g_pd[NH * (NN / 2)];      // per j-pair dst2
__device__ uint2    g_pee[NH * (NN / 2)];     // per j-pair (Ed2, Ed2^0.2) packed

__device__ __forceinline__ uint32_t smem_u32(const void* p) {
    uint32_t a;
    asm("{ .reg .u64 t; cvta.to.shared.u64 t, %1; cvt.u32.u64 %0, t; }" : "=r"(a) : "l"(p));
    return a;
}
__device__ __forceinline__ unsigned h2u(__half2 v) {
    return *reinterpret_cast<unsigned*>(&v);
}
__device__ __forceinline__ __half2 u2h(unsigned v) {
    return *reinterpret_cast<__half2*>(&v);
}
__device__ __forceinline__ void ldsm4(uint32_t& r0, uint32_t& r1, uint32_t& r2, uint32_t& r3,
                                      uint32_t addr) {
    asm volatile("ldmatrix.sync.aligned.m8n8.x4.shared.b16 {%0,%1,%2,%3}, [%4];"
                 : "=r"(r0), "=r"(r1), "=r"(r2), "=r"(r3) : "r"(addr));
}
__device__ __forceinline__ void mma16816(float* d, const uint32_t* a, const uint32_t* b) {
    asm volatile(
        "mma.sync.aligned.m16n8k16.row.col.f32.f16.f16.f32 "
        "{%0,%1,%2,%3}, {%4,%5,%6,%7}, {%8,%9}, {%0,%1,%2,%3};"
        : "+f"(d[0]), "+f"(d[1]), "+f"(d[2]), "+f"(d[3])
        : "r"(a[0]), "r"(a[1]), "r"(a[2]), "r"(a[3]), "r"(b[0]), "r"(b[1]));
}
#define CP_ASYNC16(smem, gmem) \
    asm volatile("cp.async.cg.shared.global [%0], [%1], 16;" :: "r"(smem), "l"(gmem) : "memory")
#define CP_COMMIT() asm volatile("cp.async.commit_group;" ::: "memory")
#define CP_WAIT2()  asm volatile("cp.async.wait_group 2;" ::: "memory")

// ============================================================
__global__ void k_nop() {}   // ncu launch-index shim

// ============================================================
// K1: cvtW (blocks 0..255) + ws (blocks 256..287)
// ============================================================
__global__ __launch_bounds__(256) void k_wprep(const float* __restrict__ W,
                                               const float* __restrict__ a) {
    __shared__ float Ts[32][33];
    int b = blockIdx.x, tid = threadIdx.x;
    if (b < 256) {
        int k0 = (b >> 4) * 32, c0 = (b & 15) * 32;
        int tx = tid & 31, ty = tid >> 5;
#pragma unroll
        for (int q = 0; q < 4; q++) {
            int r = ty + q * 8;
            Ts[r][tx] = W[(k0 + r) * CF + c0 + tx];
        }
        __syncthreads();
#pragma unroll
        for (int q = 0; q < 4; q++) {
            int cy = ty + q * 8;
            g_W16T[(c0 + cy) * KF + k0 + tx] = __float2half(Ts[tx][cy]);
        }
    } else {
        __shared__ float as[128];
        if (tid < 128) as[tid] = a[tid];
        __syncthreads();
        int idx = (b - 256) * 256 + tid;          // 8192 total
        int hd = idx & 15, k = idx >> 4;
        int h = hd >> 1, d = hd & 1;
        const float* wr = W + k * CF + h * OF;
        const float* av = as + d * OF;
        float s = 0.f;
#pragma unroll 16
        for (int f = 0; f < OF; f++) s += wr[f] * av[f];
        g_wst[hd * KF + k] = s;
    }
}

// ============================================================
// K2: gemm16 -> WhT direct (blocks 0..255) + adj/attrs (256..4351)
// ============================================================
#define GASTR 72
#define GBSTR 72
__global__ __launch_bounds__(256) void k_big(const float* __restrict__ h,
                                             const int* __restrict__ adj) {
    __shared__ __half sm2[128 * GASTR + 64 * GBSTR];
    int bidx = blockIdx.x, tid = threadIdx.x;

    if (bidx < 256) {
        // ---------------- gemm16, output transposed to WhT ----------------
        __half* As = sm2;
        __half* Bs = sm2 + 128 * GASTR;
        int wid = tid >> 5, lane = tid & 31;
        int hh = bidx & 7;                 // head
        int c0 = hh * 64;                  // col base in CF
        int n0 = (bidx >> 3) * 128;        // row base
        float acc[8][4];
#pragma unroll
        for (int nt = 0; nt < 8; nt++)
#pragma unroll
            for (int q = 0; q < 4; q++) acc[nt][q] = 0.f;
        uint32_t aAddr = smem_u32(As) + (wid * 16 + (lane & 15)) * (GASTR * 2) + (lane >> 4) * 16;
        uint32_t bAddr = smem_u32(Bs) + (((lane & 7) + ((lane >> 4) & 1) * 8)) * (GBSTR * 2)
                       + ((lane >> 3) & 1) * 16;

        for (int k0 = 0; k0 < KF; k0 += 64) {
            __syncthreads();
#pragma unroll
            for (int q = 0; q < 8; q++) {
                int lin = tid + q * 256;
                int rr = lin >> 4, kq = (lin & 15) * 4;
                float4 v = *(const float4*)(h + (size_t)(n0 + rr) * KF + k0 + kq);
                *(__half2*)&As[rr * GASTR + kq]     = __floats2half2_rn(v.x, v.y);
                *(__half2*)&As[rr * GASTR + kq + 2] = __floats2half2_rn(v.z, v.w);
            }
#pragma unroll
            for (int q = 0; q < 2; q++) {
                int lin = tid + q * 256;
                int cc = lin >> 3, kq = (lin & 7) * 8;
                uint4 v = *(const uint4*)&g_W16T[(c0 + cc) * KF + k0 + kq];
                *(uint4*)&Bs[cc * GBSTR + kq] = v;
            }
            __syncthreads();
#pragma unroll
            for (int kc = 0; kc < 4; kc++) {
                uint32_t aa[4];
                ldsm4(aa[0], aa[1], aa[2], aa[3], aAddr + kc * 32);
                uint32_t b[16];
#pragma unroll
                for (int nq = 0; nq < 4; nq++)
                    ldsm4(b[nq * 4], b[nq * 4 + 1], b[nq * 4 + 2], b[nq * 4 + 3],
                          bAddr + nq * 16 * (GBSTR * 2) + kc * 32);
#pragma unroll
                for (int nt = 0; nt < 8; nt++) mma16816(acc[nt], aa, &b[nt * 2]);
            }
        }

        // epilogue: transpose via smem (reuse As region), write WhT [h][f][n]
        __syncthreads();
        {
            __half* Tt = sm2;              // 64 f x 130 stride halves = 16.6 KB
            int rl = wid * 16 + (lane >> 2);
            int cl = (lane & 3) * 2;
#pragma unroll
            for (int nt = 0; nt < 8; nt++) {
                int f0 = cl + nt * 8;
                Tt[f0 * 130 + rl]           = __float2half(acc[nt][0]);
                Tt[(f0 + 1) * 130 + rl]     = __float2half(acc[nt][1]);
                Tt[f0 * 130 + rl + 8]       = __float2half(acc[nt][2]);
                Tt[(f0 + 1) * 130 + rl + 8] = __float2half(acc[nt][3]);
            }
            __syncthreads();
#pragma unroll
            for (int q = 0; q < 16; q++) {
                int lin = tid + q * 256;
                int f = lin >> 6, n2 = (lin & 63) * 2;
                __half2 hv = __halves2half2(Tt[f * 130 + n2], Tt[f * 130 + n2 + 1]);
                *(__half2*)&g_WhT[(hh * OF + f) * NN + n0 + n2] = hv;
            }
        }
    } else {
        // ---------------- adj pack + attrs, node b ----------------
        int b = bidx - 256;
        int w = tid >> 5, lane = tid & 31;
#pragma unroll
        for (int q = 0; q < 16; q++) {
            int wd = w * 16 + q;
            int j = wd * 32 + lane;
            unsigned bt = __ballot_sync(0xFFFFFFFFu, adj[(size_t)b * NN + j] > 0);
            if (lane == 0) g_bits[b * 128 + wd] = bt;
        }
        {
            const float* hr  = h + (size_t)b * KF;
            const float* wsS = g_wst + (2 * w) * KF;
            const float* wsD = g_wst + (2 * w + 1) * KF;
            float s = 0.f, d = 0.f;
#pragma unroll
            for (int t = 0; t < 16; t++) {
                float hv = hr[lane + 32 * t];
                s += hv * wsS[lane + 32 * t];
                d += hv * wsD[lane + 32 * t];
            }
#pragma unroll
            for (int o = 16; o; o >>= 1) {
                s += __shfl_xor_sync(0xFFFFFFFFu, s, o);
                d += __shfl_xor_sync(0xFFFFFFFFu, d, o);
            }
            if (lane == 0) {
                g_attrS[w * NN + b] = make_float4(s, expf(s) * 0.0625f,
                                                  expf(0.2f * s) * 0.0625f, 0.f);
                int pi = w * (NN / 2) + (b >> 1);
                ((__half*)&g_pd[pi])[b & 1]  = __float2half(d);
                __half* ep = (__half*)&g_pee[pi];
                ep[b & 1]     = __float2half(expf(d));
                ep[2 + (b & 1)] = __float2half(expf(0.2f * d));
            }
        }
    }
}

// ============================================================
// GAT: register A-fragments (split load/compute prefetch),
// B staged via cp.async 4-stage pipeline, 2 CTAs/SM
// ============================================================
#define BSTR 72
#define BBUF 9216                       // 64*72*2
#define SM_TOT (4 * BBUF + 128)

__global__ __launch_bounds__(256, 2) void k_gat_mma(float* __restrict__ out) {
    extern __shared__ char sm[];
    uint32_t sb = smem_u32(sm);

    int tid = threadIdx.x, wid = tid >> 5, lane = tid & 31;
    int head = blockIdx.x, i0 = blockIdx.y << 7;
    int r = lane >> 2, t = lane & 3;
    int t2 = t << 1;

    int row0 = i0 + wid * 16 + r;
    __half2 isrc[2], ies[2], ies2[2];
    {
        float4 v0 = g_attrS[head * NN + row0];
        float4 v1 = g_attrS[head * NN + row0 + 8];
        isrc[0] = __float2half2_rn(v0.x); ies[0] = __float2half2_rn(v0.y);
        ies2[0] = __float2half2_rn(v0.z);
        isrc[1] = __float2half2_rn(v1.x); ies[1] = __float2half2_rn(v1.y);
        ies2[1] = __float2half2_rn(v1.z);
    }
    const unsigned* bitR0 = g_bits + (size_t)row0 * 128;
    const unsigned* bitR1 = bitR0 + 8 * 128;
    const int hpo = head * (NN / 2);

    float acc[8][4], accz[4];
#pragma unroll
    for (int nt = 0; nt < 8; nt++)
#pragma unroll
        for (int q = 0; q < 4; q++) acc[nt][q] = 0.f;
#pragma unroll
    for (int q = 0; q < 4; q++) accz[q] = 0.f;

    uint32_t bz[2];
    bz[0] = bz[1] = (lane < 4) ? 0x3C003C00u : 0u;

    uint32_t bAddr = sb + (((lane & 7) + ((lane >> 4) & 1) * 8)) * (BSTR * 2)
                   + ((lane >> 3) & 1) * 16;

    auto stageB = [&](int j0, int bufn) {
#pragma unroll
        for (int q = 0; q < 2; q++) {
            int lin = tid + q * 256;
            int f = lin >> 3, c = lin & 7;
            const __half* gp = &g_WhT[(head * OF + f) * NN + j0 + c * 8];
            uint32_t sp = sb + bufn * BBUF + (uint32_t)(f * BSTR + c * 8) * 2;
            CP_ASYNC16(sp, gp);
        }
    };

    __half2 nJd[8];
    uint2 nJee[8];
    uint2 nbw0, nbw1;

    auto genLoad = [&](int s1) {
        nbw0 = *(const uint2*)(bitR0 + s1 * 2);
        nbw1 = *(const uint2*)(bitR1 + s1 * 2);
        int base = hpo + (s1 << 5) + t;
#pragma unroll
        for (int kc = 0; kc < 4; kc++) {
            nJd[kc * 2]      = g_pd[base + kc * 8];
            nJd[kc * 2 + 1]  = g_pd[base + kc * 8 + 4];
            nJee[kc * 2]     = g_pee[base + kc * 8];
            nJee[kc * 2 + 1] = g_pee[base + kc * 8 + 4];
        }
    };

    const __half2 zero2 = __float2half2_rn(0.f);
    auto val = [&](int rowIdx, __half2 dst2, uint2 ee, unsigned sel) -> uint32_t {
        unsigned g = __hgt2_mask(__hadd2(isrc[rowIdx], dst2), zero2);
        unsigned v = (h2u(__hmul2(ies[rowIdx], u2h(ee.x))) & g)
                   | (h2u(__hmul2(ies2[rowIdx], u2h(ee.y))) & ~g);
        unsigned mask = (sel & 1u) * 0x0000FFFFu + (sel & 2u) * 0x7FFF8000u;
        return v & mask;
    };

    uint32_t frag[4][4];
    auto genCompute = [&]() {
#pragma unroll
        for (int kc = 0; kc < 4; kc++) {
            unsigned w0 = (kc < 2) ? nbw0.x : nbw0.y;
            unsigned w1 = (kc < 2) ? nbw1.x : nbw1.y;
            int shA = ((kc & 1) << 4) + t2;
            frag[kc][0] = val(0, nJd[kc * 2],     nJee[kc * 2],     (w0 >> shA) & 3u);
            frag[kc][1] = val(1, nJd[kc * 2],     nJee[kc * 2],     (w1 >> shA) & 3u);
            frag[kc][2] = val(0, nJd[kc * 2 + 1], nJee[kc * 2 + 1], (w0 >> (shA + 8)) & 3u);
            frag[kc][3] = val(1, nJd[kc * 2 + 1], nJee[kc * 2 + 1], (w1 >> (shA + 8)) & 3u);
        }
    };

    stageB(0, 0);   CP_COMMIT();
    stageB(64, 1);  CP_COMMIT();
    stageB(128, 2); CP_COMMIT();
    genLoad(0);
    genCompute();

    for (int s = 0; s < 64; s++) {
        CP_WAIT2();
        __syncthreads();
        if (s < 63) genLoad(s + 1);
        if (s + 3 < 64) stageB((s + 3) << 6, (s + 3) & 3);
        CP_COMMIT();

        int buf = s & 3;
#pragma unroll
        for (int kc = 0; kc < 4; kc++) {
            uint32_t b[16];
#pragma unroll
            for (int nq = 0; nq < 4; nq++)
                ldsm4(b[nq * 4], b[nq * 4 + 1], b[nq * 4 + 2], b[nq * 4 + 3],
                      bAddr + buf * BBUF + nq * 16 * (BSTR * 2) + kc * 32);
#pragma unroll
            for (int nt = 0; nt < 8; nt++)
                mma16816(acc[nt], frag[kc], &b[nt * 2]);
            mma16816(accz, frag[kc], bz);
        }

        if (s < 63) genCompute();
    }

    float z0 = __shfl_sync(0xFFFFFFFFu, accz[0], lane & 28);
    float z1 = __shfl_sync(0xFFFFFFFFu, accz[2], lane & 28);
    float inv0 = 1.0f / z0;
    float inv1 = 1.0f / z1;

    {
        float* o0 = out + (size_t)row0 * CF + head * OF + t2;
        float* o1 = o0 + 8 * CF;
#pragma unroll
        for (int nt = 0; nt < 8; nt++) {
            float v0 = acc[nt][0] * inv0, v1 = acc[nt][1] * inv0;
            float v2 = acc[nt][2] * inv1, v3 = acc[nt][3] * inv1;
            v0 = v0 > 0.f ? v0 : (expf(v0) - 1.0f);
            v1 = v1 > 0.f ? v1 : (expf(v1) - 1.0f);
            v2 = v2 > 0.f ? v2 : (expf(v2) - 1.0f);
            v3 = v3 > 0.f ? v3 : (expf(v3) - 1.0f);
            *(float2*)(o0 + nt * 8) = make_float2(v0, v1);
            *(float2*)(o1 + nt * 8) = make_float2(v2, v3);
        }
    }
}

// ============================================================
extern "C" void kernel_launch(void* const* d_in, const int* in_sizes, int n_in,
                              void* d_out, int out_size) {
    const float* h   = (const float*)d_in[0];
    const int*   adj = (const int*)d_in[1];
    const float* W   = (const float*)d_in[2];
    const float* a   = (const float*)d_in[3];
    float* out = (float*)d_out;

    k_nop<<<1, 32>>>();
    k_wprep<<<288, 256>>>(W, a);          // cvtW + ws
    k_big<<<4352, 256>>>(h, adj);         // gemm16->WhT + adj pack + attrs

    cudaFuncSetAttribute(k_gat_mma, cudaFuncAttributeMaxDynamicSharedMemorySize, SM_TOT);
    k_gat_mma<<<dim3(NH, NN / 128), 256, SM_TOT>>>(out);   // launch #4 -> ncu capture
}

// round 17
// speedup vs baseline: 1.5726x; 1.0318x over previous
#include <cuda_runtime.h>
#include <cuda_fp16.h>
#include <math.h>
#include <stdint.h>

#define NN   4096
#define KF   512     // IN_F
#define CF   512     // OUT_F * N_HEADS
#define NH   8
#define OF   64

// ---- scratch (device globals; no allocation allowed) ----
__device__ __half   g_W16T[CF * KF];          // 512 KB  W fp16 transposed [c][k]
__device__ __half   g_h16[(size_t)NN * KF];   // 4 MB    h fp16 [n][k]
__device__ float    g_wst[16 * KF];           // 32 KB   ws_t[h*2+d][k]
__device__ __half   g_WhT[NH * OF * NN];      // 4 MB    values transposed [h][f][n]
__device__ unsigned g_bits[NN * 128];         // 2 MB    packed adj
__device__ float4   g_attrS[NH * NN];         // (src, Es/16, Es2/16, 0)
__device__ __half2  g_pd[NH * (NN / 2)];      // per j-pair dst2
__device__ uint2    g_pee[NH * (NN / 2)];     // per j-pair (Ed2, Ed2^0.2) packed

__device__ __forceinline__ uint32_t smem_u32(const void* p) {
    uint32_t a;
    asm("{ .reg .u64 t; cvta.to.shared.u64 t, %1; cvt.u32.u64 %0, t; }" : "=r"(a) : "l"(p));
    return a;
}
__device__ __forceinline__ unsigned h2u(__half2 v) {
    return *reinterpret_cast<unsigned*>(&v);
}
__device__ __forceinline__ __half2 u2h(unsigned v) {
    return *reinterpret_cast<__half2*>(&v);
}
__device__ __forceinline__ void ldsm4(uint32_t& r0, uint32_t& r1, uint32_t& r2, uint32_t& r3,
                                      uint32_t addr) {
    asm volatile("ldmatrix.sync.aligned.m8n8.x4.shared.b16 {%0,%1,%2,%3}, [%4];"
                 : "=r"(r0), "=r"(r1), "=r"(r2), "=r"(r3) : "r"(addr));
}
__device__ __forceinline__ void mma16816(float* d, const uint32_t* a, const uint32_t* b) {
    asm volatile(
        "mma.sync.aligned.m16n8k16.row.col.f32.f16.f16.f32 "
        "{%0,%1,%2,%3}, {%4,%5,%6,%7}, {%8,%9}, {%0,%1,%2,%3};"
        : "+f"(d[0]), "+f"(d[1]), "+f"(d[2]), "+f"(d[3])
        : "r"(a[0]), "r"(a[1]), "r"(a[2]), "r"(a[3]), "r"(b[0]), "r"(b[1]));
}
#define CP_ASYNC16(smem, gmem) \
    asm volatile("cp.async.cg.shared.global [%0], [%1], 16;" :: "r"(smem), "l"(gmem) : "memory")
#define CP_COMMIT() asm volatile("cp.async.commit_group;" ::: "memory")
#define CP_WAIT2()  asm volatile("cp.async.wait_group 2;" ::: "memory")
#define CP_WAIT0()  asm volatile("cp.async.wait_group 0;" ::: "memory")

// ============================================================
__global__ void k_nop() {}   // ncu launch-index shim

// ============================================================
// K1: cvtW (0..255) + ws (256..287) + h->fp16 (288..1311)
// ============================================================
__global__ __launch_bounds__(256) void k_wprep(const float* __restrict__ W,
                                               const float* __restrict__ a,
                                               const float* __restrict__ hsrc) {
    __shared__ float Ts[32][33];
    int b = blockIdx.x, tid = threadIdx.x;
    if (b < 256) {
        int k0 = (b >> 4) * 32, c0 = (b & 15) * 32;
        int tx = tid & 31, ty = tid >> 5;
#pragma unroll
        for (int q = 0; q < 4; q++) {
            int r = ty + q * 8;
            Ts[r][tx] = W[(k0 + r) * CF + c0 + tx];
        }
        __syncthreads();
#pragma unroll
        for (int q = 0; q < 4; q++) {
            int cy = ty + q * 8;
            g_W16T[(c0 + cy) * KF + k0 + tx] = __float2half(Ts[tx][cy]);
        }
    } else if (b < 288) {
        __shared__ float as[128];
        if (tid < 128) as[tid] = a[tid];
        __syncthreads();
        int idx = (b - 256) * 256 + tid;          // 8192 total
        int hd = idx & 15, k = idx >> 4;
        int h = hd >> 1, d = hd & 1;
        const float* wr = W + k * CF + h * OF;
        const float* av = as + d * OF;
        float s = 0.f;
#pragma unroll 16
        for (int f = 0; f < OF; f++) s += wr[f] * av[f];
        g_wst[hd * KF + k] = s;
    } else {
        // h -> fp16, 2048 elems per block (same rounding as before)
        size_t idx = (size_t)(b - 288) * 2048 + tid * 8;
        float4 v0 = *(const float4*)(hsrc + idx);
        float4 v1 = *(const float4*)(hsrc + idx + 4);
        __half2 p0 = __floats2half2_rn(v0.x, v0.y);
        __half2 p1 = __floats2half2_rn(v0.z, v0.w);
        __half2 p2 = __floats2half2_rn(v1.x, v1.y);
        __half2 p3 = __floats2half2_rn(v1.z, v1.w);
        uint4 pk = make_uint4(h2u(p0), h2u(p1), h2u(p2), h2u(p3));
        *(uint4*)&g_h16[idx] = pk;
    }
}

// ============================================================
// K2: gemm16 via cp.async (blocks 0..255) + adj/attrs (256..4351)
// gemm writes WhT directly (transposed epilogue)
// ============================================================
#define GSTR 72
#define STG_H (192 * GSTR)               // halves per stage (A 128 + B 64 rows)
#define SM2_TOT (2 * STG_H * 2)          // 55296 bytes

__global__ __launch_bounds__(256) void k_big(const float* __restrict__ h,
                                             const int* __restrict__ adj) {
    extern __shared__ __half dsm[];
    int bidx = blockIdx.x, tid = threadIdx.x;

    if (bidx < 256) {
        // ---------------- gemm16, cp.async 2-stage, output -> WhT ----------------
        uint32_t sb = smem_u32(dsm);
        int wid = tid >> 5, lane = tid & 31;
        int hh = bidx & 7;
        int c0 = hh * 64;
        int n0 = (bidx >> 3) * 128;
        float acc[8][4];
#pragma unroll
        for (int nt = 0; nt < 8; nt++)
#pragma unroll
            for (int q = 0; q < 4; q++) acc[nt][q] = 0.f;

        uint32_t aAddr = sb + (wid * 16 + (lane & 15)) * (GSTR * 2) + (lane >> 4) * 16;
        uint32_t bAddr = sb + 128 * GSTR * 2
                       + (((lane & 7) + ((lane >> 4) & 1) * 8)) * (GSTR * 2)
                       + ((lane >> 3) & 1) * 16;

        auto issueChunk = [&](int k0, int stg) {
            uint32_t base = sb + stg * (STG_H * 2);
#pragma unroll
            for (int q = 0; q < 4; q++) {          // A: 128 rows x 8 chunks
                int lin = tid + q * 256;
                int f = lin >> 3, c = lin & 7;
                const __half* gp = &g_h16[(size_t)(n0 + f) * KF + k0 + c * 8];
                CP_ASYNC16(base + (uint32_t)(f * GSTR + c * 8) * 2, gp);
            }
#pragma unroll
            for (int q = 0; q < 2; q++) {          // B: 64 rows x 8 chunks
                int lin = tid + q * 256;
                int cc = lin >> 3, c = lin & 7;
                const __half* gp = &g_W16T[(c0 + cc) * KF + k0 + c * 8];
                CP_ASYNC16(base + (uint32_t)(128 * GSTR + cc * GSTR + c * 8) * 2, gp);
            }
        };

        issueChunk(0, 0);
        CP_COMMIT();

        for (int i = 0; i < 8; i++) {
            CP_WAIT0();
            __syncthreads();               // chunk i visible; compute(i-1) done
            if (i < 7) {
                issueChunk((i + 1) * 64, (i + 1) & 1);
                CP_COMMIT();
            }
            uint32_t stOff = (i & 1) * (STG_H * 2);
#pragma unroll
            for (int kc = 0; kc < 4; kc++) {
                uint32_t aa[4];
                ldsm4(aa[0], aa[1], aa[2], aa[3], aAddr + stOff + kc * 32);
                uint32_t b[16];
#pragma unroll
                for (int nq = 0; nq < 4; nq++)
                    ldsm4(b[nq * 4], b[nq * 4 + 1], b[nq * 4 + 2], b[nq * 4 + 3],
                          bAddr + stOff + nq * 16 * (GSTR * 2) + kc * 32);
#pragma unroll
                for (int nt = 0; nt < 8; nt++) mma16816(acc[nt], aa, &b[nt * 2]);
            }
        }

        // epilogue: transpose via smem, write WhT [h][f][n]
        __syncthreads();
        {
            __half* Tt = dsm;              // 64 x 130 halves
            int rl = wid * 16 + (lane >> 2);
            int cl = (lane & 3) * 2;
#pragma unroll
            for (int nt = 0; nt < 8; nt++) {
                int f0 = cl + nt * 8;
                Tt[f0 * 130 + rl]           = __float2half(acc[nt][0]);
                Tt[(f0 + 1) * 130 + rl]     = __float2half(acc[nt][1]);
                Tt[f0 * 130 + rl + 8]       = __float2half(acc[nt][2]);
                Tt[(f0 + 1) * 130 + rl + 8] = __float2half(acc[nt][3]);
            }
            __syncthreads();
#pragma unroll
            for (int q = 0; q < 16; q++) {
                int lin = tid + q * 256;
                int f = lin >> 6, n2 = (lin & 63) * 2;
                __half2 hv = __halves2half2(Tt[f * 130 + n2], Tt[f * 130 + n2 + 1]);
                *(__half2*)&g_WhT[(hh * OF + f) * NN + n0 + n2] = hv;
            }
        }
    } else {
        // ---------------- adj pack + attrs, node b ----------------
        int b = bidx - 256;
        int w = tid >> 5, lane = tid & 31;
#pragma unroll
        for (int q = 0; q < 16; q++) {
            int wd = w * 16 + q;
            int j = wd * 32 + lane;
            unsigned bt = __ballot_sync(0xFFFFFFFFu, adj[(size_t)b * NN + j] > 0);
            if (lane == 0) g_bits[b * 128 + wd] = bt;
        }
        {
            const float* hr  = h + (size_t)b * KF;
            const float* wsS = g_wst + (2 * w) * KF;
            const float* wsD = g_wst + (2 * w + 1) * KF;
            float s = 0.f, d = 0.f;
#pragma unroll
            for (int t = 0; t < 16; t++) {
                float hv = hr[lane + 32 * t];
                s += hv * wsS[lane + 32 * t];
                d += hv * wsD[lane + 32 * t];
            }
#pragma unroll
            for (int o = 16; o; o >>= 1) {
                s += __shfl_xor_sync(0xFFFFFFFFu, s, o);
                d += __shfl_xor_sync(0xFFFFFFFFu, d, o);
            }
            if (lane == 0) {
                g_attrS[w * NN + b] = make_float4(s, expf(s) * 0.0625f,
                                                  expf(0.2f * s) * 0.0625f, 0.f);
                int pi = w * (NN / 2) + (b >> 1);
                ((__half*)&g_pd[pi])[b & 1]  = __float2half(d);
                __half* ep = (__half*)&g_pee[pi];
                ep[b & 1]       = __float2half(expf(d));
                ep[2 + (b & 1)] = __float2half(expf(0.2f * d));
            }
        }
    }
}

// ============================================================
// GAT: register A-fragments (split load/compute prefetch),
// B staged via cp.async 4-stage pipeline, 2 CTAs/SM  (unchanged)
// ============================================================
#define BSTR 72
#define BBUF 9216                       // 64*72*2
#define SM_TOT (4 * BBUF + 128)

__global__ __launch_bounds__(256, 2) void k_gat_mma(float* __restrict__ out) {
    extern __shared__ char sm[];
    uint32_t sb = smem_u32(sm);

    int tid = threadIdx.x, wid = tid >> 5, lane = tid & 31;
    int head = blockIdx.x, i0 = blockIdx.y << 7;
    int r = lane >> 2, t = lane & 3;
    int t2 = t << 1;

    int row0 = i0 + wid * 16 + r;
    __half2 isrc[2], ies[2], ies2[2];
    {
        float4 v0 = g_attrS[head * NN + row0];
        float4 v1 = g_attrS[head * NN + row0 + 8];
        isrc[0] = __float2half2_rn(v0.x); ies[0] = __float2half2_rn(v0.y);
        ies2[0] = __float2half2_rn(v0.z);
        isrc[1] = __float2half2_rn(v1.x); ies[1] = __float2half2_rn(v1.y);
        ies2[1] = __float2half2_rn(v1.z);
    }
    const unsigned* bitR0 = g_bits + (size_t)row0 * 128;
    const unsigned* bitR1 = bitR0 + 8 * 128;
    const int hpo = head * (NN / 2);

    float acc[8][4], accz[4];
#pragma unroll
    for (int nt = 0; nt < 8; nt++)
#pragma unroll
        for (int q = 0; q < 4; q++) acc[nt][q] = 0.f;
#pragma unroll
    for (int q = 0; q < 4; q++) accz[q] = 0.f;

    uint32_t bz[2];
    bz[0] = bz[1] = (lane < 4) ? 0x3C003C00u : 0u;

    uint32_t bAddr = sb + (((lane & 7) + ((lane >> 4) & 1) * 8)) * (BSTR * 2)
                   + ((lane >> 3) & 1) * 16;

    auto stageB = [&](int j0, int bufn) {
#pragma unroll
        for (int q = 0; q < 2; q++) {
            int lin = tid + q * 256;
            int f = lin >> 3, c = lin & 7;
            const __half* gp = &g_WhT[(head * OF + f) * NN + j0 + c * 8];
            uint32_t sp = sb + bufn * BBUF + (uint32_t)(f * BSTR + c * 8) * 2;
            CP_ASYNC16(sp, gp);
        }
    };

    __half2 nJd[8];
    uint2 nJee[8];
    uint2 nbw0, nbw1;

    auto genLoad = [&](int s1) {
        nbw0 = *(const uint2*)(bitR0 + s1 * 2);
        nbw1 = *(const uint2*)(bitR1 + s1 * 2);
        int base = hpo + (s1 << 5) + t;
#pragma unroll
        for (int kc = 0; kc < 4; kc++) {
            nJd[kc * 2]      = g_pd[base + kc * 8];
            nJd[kc * 2 + 1]  = g_pd[base + kc * 8 + 4];
            nJee[kc * 2]     = g_pee[base + kc * 8];
            nJee[kc * 2 + 1] = g_pee[base + kc * 8 + 4];
        }
    };

    const __half2 zero2 = __float2half2_rn(0.f);
    auto val = [&](int rowIdx, __half2 dst2, uint2 ee, unsigned sel) -> uint32_t {
        unsigned g = __hgt2_mask(__hadd2(isrc[rowIdx], dst2), zero2);
        unsigned v = (h2u(__hmul2(ies[rowIdx], u2h(ee.x))) & g)
                   | (h2u(__hmul2(ies2[rowIdx], u2h(ee.y))) & ~g);
        unsigned mask = (sel & 1u) * 0x0000FFFFu + (sel & 2u) * 0x7FFF8000u;
        return v & mask;
    };

    uint32_t frag[4][4];
    auto genCompute = [&]() {
#pragma unroll
        for (int kc = 0; kc < 4; kc++) {
            unsigned w0 = (kc < 2) ? nbw0.x : nbw0.y;
            unsigned w1 = (kc < 2) ? nbw1.x : nbw1.y;
            int shA = ((kc & 1) << 4) + t2;
            frag[kc][0] = val(0, nJd[kc * 2],     nJee[kc * 2],     (w0 >> shA) & 3u);
            frag[kc][1] = val(1, nJd[kc * 2],     nJee[kc * 2],     (w1 >> shA) & 3u);
            frag[kc][2] = val(0, nJd[kc * 2 + 1], nJee[kc * 2 + 1], (w0 >> (shA + 8)) & 3u);
            frag[kc][3] = val(1, nJd[kc * 2 + 1], nJee[kc * 2 + 1], (w1 >> (shA + 8)) & 3u);
        }
    };

    stageB(0, 0);   CP_COMMIT();
    stageB(64, 1);  CP_COMMIT();
    stageB(128, 2); CP_COMMIT();
    genLoad(0);
    genCompute();

    for (int s = 0; s < 64; s++) {
        CP_WAIT2();
        __syncthreads();
        if (s < 63) genLoad(s + 1);
        if (s + 3 < 64) stageB((s + 3) << 6, (s + 3) & 3);
        CP_COMMIT();

        int buf = s & 3;
#pragma unroll
        for (int kc = 0; kc < 4; kc++) {
            uint32_t b[16];
#pragma unroll
            for (int nq = 0; nq < 4; nq++)
                ldsm4(b[nq * 4], b[nq * 4 + 1], b[nq * 4 + 2], b[nq * 4 + 3],
                      bAddr + buf * BBUF + nq * 16 * (BSTR * 2) + kc * 32);
#pragma unroll
            for (int nt = 0; nt < 8; nt++)
                mma16816(acc[nt], frag[kc], &b[nt * 2]);
            mma16816(accz, frag[kc], bz);
        }

        if (s < 63) genCompute();
    }

    float z0 = __shfl_sync(0xFFFFFFFFu, accz[0], lane & 28);
    float z1 = __shfl_sync(0xFFFFFFFFu, accz[2], lane & 28);
    float inv0 = 1.0f / z0;
    float inv1 = 1.0f / z1;

    {
        float* o0 = out + (size_t)row0 * CF + head * OF + t2;
        float* o1 = o0 + 8 * CF;
#pragma unroll
        for (int nt = 0; nt < 8; nt++) {
            float v0 = acc[nt][0] * inv0, v1 = acc[nt][1] * inv0;
            float v2 = acc[nt][2] * inv1, v3 = acc[nt][3] * inv1;
            v0 = v0 > 0.f ? v0 : (expf(v0) - 1.0f);
            v1 = v1 > 0.f ? v1 : (expf(v1) - 1.0f);
            v2 = v2 > 0.f ? v2 : (expf(v2) - 1.0f);
            v3 = v3 > 0.f ? v3 : (expf(v3) - 1.0f);
            *(float2*)(o0 + nt * 8) = make_float2(v0, v1);
            *(float2*)(o1 + nt * 8) = make_float2(v2, v3);
        }
    }
}

// ============================================================
extern "C" void kernel_launch(void* const* d_in, const int* in_sizes, int n_in,
                              void* d_out, int out_size) {
    const float* h   = (const float*)d_in[0];
    const int*   adj = (const int*)d_in[1];
    const float* W   = (const float*)d_in[2];
    const float* a   = (const float*)d_in[3];
    float* out = (float*)d_out;

    k_nop<<<1, 32>>>();
    k_wprep<<<1312, 256>>>(W, a, h);            // cvtW + ws + h->fp16

    cudaFuncSetAttribute(k_big, cudaFuncAttributeMaxDynamicSharedMemorySize, SM2_TOT);
    k_big<<<4352, 256, SM2_TOT>>>(h, adj);      // gemm16(cp.async)->WhT + pack + attrs

    cudaFuncSetAttribute(k_gat_mma, cudaFuncAttributeMaxDynamicSharedMemorySize, SM_TOT);
    k_gat_mma<<<dim3(NH, NN / 128), 256, SM_TOT>>>(out);   // launch #4 -> ncu capture
}